// round 2
// baseline (speedup 1.0000x reference)
#include <cuda_runtime.h>
#include <cuda_bf16.h>
#include <math.h>

#define NN   40000
#define NE   640000
#define FIN  512
#define HH   128
#define CO   40

// ---------------- scratch (device globals) ----------------
__device__ __align__(16) float g_xh [NN*HH];
__device__ __align__(16) float g_tx1[NN*HH];
__device__ __align__(16) float g_s  [NN*HH];
__device__ __align__(16) float g_t1 [NN*HH];
__device__ __align__(16) float g_xc [NN*HH];
__device__ float g_deg   [NN];
__device__ float g_dis   [NN];
__device__ float g_loopw [NN];
__device__ float g_invcnt[NN];

// ---------------- graph prep ----------------
__global__ void prep_zero_kernel() {
    int n = blockIdx.x * blockDim.x + threadIdx.x;
    if (n < NN) { g_deg[n] = 0.0f; g_loopw[n] = 1.0f; g_invcnt[n] = 0.0f; }
}

__global__ void prep_edge_kernel(const int* __restrict__ ei, const float* __restrict__ w) {
    int e = blockIdx.x * blockDim.x + threadIdx.x;
    if (e >= NE) return;
    int s = ei[e], d = ei[NE + e];
    float we = w[e];
    if (s != d) {
        atomicAdd(&g_deg[s], we);
        atomicAdd(&g_invcnt[d], 1.0f);
    } else {
        g_loopw[s] = we;
    }
}

__global__ void prep_node_kernel() {
    int n = blockIdx.x * blockDim.x + threadIdx.x;
    if (n >= NN) return;
    float dg = g_deg[n];
    g_dis[n]    = (dg > 0.0f) ? rsqrtf(dg) : 0.0f;
    g_invcnt[n] = 1.0f / (g_invcnt[n] + 1.0f);
}

// ---------------- per-cell init: tx1 = 0 ; s = loop_w * xh ----------------
__global__ void init_ts_kernel(const float4* __restrict__ xh,
                               float4* __restrict__ tx1, float4* __restrict__ s) {
    int i = blockIdx.x * blockDim.x + threadIdx.x;
    if (i >= NN * (HH/4)) return;
    int n = i >> 5;
    float lw = g_loopw[n];
    float4 v = xh[i];
    tx1[i] = make_float4(0.f, 0.f, 0.f, 0.f);
    s[i]   = make_float4(v.x*lw, v.y*lw, v.z*lw, v.w*lw);
}

// ---------------- fused edge scatter ----------------
__global__ __launch_bounds__(256)
void scatter_kernel(const int* __restrict__ ei, const float* __restrict__ w,
                    const float4* __restrict__ xh,
                    float4* __restrict__ tx1, float4* __restrict__ s) {
    int gw   = (blockIdx.x * blockDim.x + threadIdx.x) >> 5;
    int lane = threadIdx.x & 31;
    if (gw >= NE) return;
    int src = ei[gw], dst = ei[NE + gw];
    if (src == dst) return;
    float we   = w[gw];
    float coef = -g_dis[src] * we * g_dis[dst];
    float4 v = xh[src * 32 + lane];
    float4 a = make_float4(v.x*coef, v.y*coef, v.z*coef, v.w*coef);
    float4 b = make_float4(v.x*we,   v.y*we,   v.z*we,   v.w*we);
    atomicAdd(&tx1[dst * 32 + lane], a);
    atomicAdd(&s  [dst * 32 + lane], b);
}

// ---------------- 128x128x16 double-buffered SGEMM, 8x8 microtile ----------------
// C[Nrows x M] = epi( A1[Nrows x K1] @ B1[K1 x M] + A2[Nrows x K2] @ B2[K2 x M] )
#define F_BIAS       1
#define F_LEAKY      2
#define F_ADDC_POST  8
#define F_ROWSCALE  16

template<int FLAGS>
__global__ __launch_bounds__(256)
void gemm128_kernel(const float* __restrict__ A1, const float* __restrict__ B1, int K1,
                    const float* __restrict__ A2, const float* __restrict__ B2, int K2,
                    const float* __restrict__ bias, float* __restrict__ C,
                    const float* __restrict__ rowscale, int Nrows, int M) {
    __shared__ float As[2][16][132];   // [k][m], padded
    __shared__ float Bs[2][16][128];   // [k][n]

    const int tid = threadIdx.x;
    const int r0  = blockIdx.x * 128;
    const int tx  = tid & 15;          // 16 col groups
    const int ty  = tid >> 4;          // 16 row groups

    float acc[8][8];
    #pragma unroll
    for (int i = 0; i < 8; i++)
        #pragma unroll
        for (int j = 0; j < 8; j++) acc[i][j] = 0.0f;

    const int nt = (K1 + K2) >> 4;     // K1,K2 multiples of 16

    // tile loader (global -> smem buf)
    auto load_tile = [&](int t, int buf) {
        int k0 = t << 4;
        const float* A; const float* B; int kk0; int Kld;
        if (k0 < K1) { A = A1; B = B1; kk0 = k0;      Kld = K1; }
        else         { A = A2; B = B2; kk0 = k0 - K1; Kld = K2; }
        // A tile: 128 rows x 16 k  (2 float4 per thread)
        #pragma unroll
        for (int i = 0; i < 2; i++) {
            int idx = tid + i * 256;            // 0..511
            int row = idx >> 2;
            int kc  = (idx & 3) << 2;
            int gr  = r0 + row;
            float4 v = make_float4(0.f,0.f,0.f,0.f);
            if (gr < Nrows) v = *(const float4*)&A[(size_t)gr * Kld + kk0 + kc];
            As[buf][kc+0][row] = v.x; As[buf][kc+1][row] = v.y;
            As[buf][kc+2][row] = v.z; As[buf][kc+3][row] = v.w;
        }
        // B tile: 16 k x 128 cols (2 float4 per thread)
        #pragma unroll
        for (int i = 0; i < 2; i++) {
            int idx = tid + i * 256;            // 0..511
            int kr  = idx >> 5;
            int col = (idx & 31) << 2;
            float4 v = make_float4(0.f,0.f,0.f,0.f);
            if (col < M) v = *(const float4*)&B[(size_t)(kk0 + kr) * M + col];
            *(float4*)&Bs[buf][kr][col] = v;
        }
    };

    load_tile(0, 0);
    __syncthreads();

    int buf = 0;
    for (int t = 0; t < nt; t++) {
        if (t + 1 < nt) load_tile(t + 1, buf ^ 1);

        #pragma unroll
        for (int kk = 0; kk < 16; kk++) {
            float4 a0 = *(const float4*)&As[buf][kk][ty*4];
            float4 a1 = *(const float4*)&As[buf][kk][64 + ty*4];
            float4 b0 = *(const float4*)&Bs[buf][kk][tx*4];
            float4 b1 = *(const float4*)&Bs[buf][kk][64 + tx*4];
            float a[8] = {a0.x,a0.y,a0.z,a0.w, a1.x,a1.y,a1.z,a1.w};
            float b[8] = {b0.x,b0.y,b0.z,b0.w, b1.x,b1.y,b1.z,b1.w};
            #pragma unroll
            for (int i = 0; i < 8; i++)
                #pragma unroll
                for (int j = 0; j < 8; j++)
                    acc[i][j] += a[i] * b[j];
        }
        __syncthreads();
        buf ^= 1;
    }

    // epilogue
    #pragma unroll
    for (int i = 0; i < 8; i++) {
        int rl  = (i < 4) ? (ty*4 + i) : (64 + ty*4 + (i - 4));
        int row = r0 + rl;
        if (row >= Nrows) continue;
        float rs = (FLAGS & F_ROWSCALE) ? rowscale[row] : 1.0f;
        #pragma unroll
        for (int jg = 0; jg < 2; jg++) {
            int col = jg ? (64 + tx*4) : (tx*4);
            if (col >= M) continue;
            size_t off = (size_t)row * M + col;
            float4 v = make_float4(acc[i][jg*4+0], acc[i][jg*4+1],
                                   acc[i][jg*4+2], acc[i][jg*4+3]);
            v.x *= rs; v.y *= rs; v.z *= rs; v.w *= rs;
            if (FLAGS & F_BIAS) {
                float4 bb = *(const float4*)&bias[col];
                v.x += bb.x; v.y += bb.y; v.z += bb.z; v.w += bb.w;
            }
            if (FLAGS & F_LEAKY) {
                v.x = (v.x > 0.f) ? v.x : 0.01f*v.x;
                v.y = (v.y > 0.f) ? v.y : 0.01f*v.y;
                v.z = (v.z > 0.f) ? v.z : 0.01f*v.z;
                v.w = (v.w > 0.f) ? v.w : 0.01f*v.w;
            }
            if (FLAGS & F_ADDC_POST) {
                float4 c = *(const float4*)&C[off];
                v.x += c.x; v.y += c.y; v.z += c.z; v.w += c.w;
            }
            *(float4*)&C[off] = v;
        }
    }
}

// ---------------- log_softmax over 40 cols, warp per row ----------------
__global__ __launch_bounds__(256)
void logsoftmax_kernel(float* __restrict__ out) {
    int row  = (blockIdx.x * blockDim.x + threadIdx.x) >> 5;
    int lane = threadIdx.x & 31;
    if (row >= NN) return;
    float* p = out + (size_t)row * CO;
    float v0 = p[lane];
    float v1 = (lane < CO - 32) ? p[32 + lane] : -3.4e38f;
    float m = fmaxf(v0, v1);
    #pragma unroll
    for (int o = 16; o > 0; o >>= 1) m = fmaxf(m, __shfl_xor_sync(0xffffffffu, m, o));
    float e = expf(v0 - m) + ((lane < CO - 32) ? expf(v1 - m) : 0.0f);
    #pragma unroll
    for (int o = 16; o > 0; o >>= 1) e += __shfl_xor_sync(0xffffffffu, e, o);
    float ls = m + logf(e);
    p[lane] = v0 - ls;
    if (lane < CO - 32) p[32 + lane] = v1 - ls;
}

// ---------------- launch ----------------
static void run_cell(const float* x_in, const int* ei, const float* w,
                     const float* pw, const float* pb,
                     const float* cw0, const float* cw1, const float* cb,
                     const float* sw, const float* sb,
                     const float* lw, const float* lb,
                     float* xh, float* tx1, float* s, float* t1, float* x_out,
                     float* invcnt, int Kin) {
    const int GB = (NN + 127) / 128;
    // 1. xh = x_in @ pw + pb
    gemm128_kernel<F_BIAS><<<GB, 256>>>(x_in, pw, Kin, nullptr, nullptr, 0,
                                        pb, xh, nullptr, NN, HH);
    // 2. tx1 = 0 ; s = loop_w * xh
    init_ts_kernel<<<(NN*(HH/4) + 255)/256, 256>>>((const float4*)xh, (float4*)tx1, (float4*)s);
    // 3. fused scatter
    scatter_kernel<<<(NE*32 + 255)/256, 256>>>(ei, w, (const float4*)xh, (float4*)tx1, (float4*)s);
    // 4. t1 = leaky(xh @ cw0 + tx1 @ cw1 + cb)      (fused two-segment GEMM)
    gemm128_kernel<F_BIAS | F_LEAKY><<<GB, 256>>>(xh, cw0, HH, tx1, cw1, HH,
                                                  cb, t1, nullptr, NN, HH);
    // 5. t1 += leaky((s * invcnt_row) @ sw + sb)
    gemm128_kernel<F_ROWSCALE | F_BIAS | F_LEAKY | F_ADDC_POST><<<GB, 256>>>(
        s, sw, HH, nullptr, nullptr, 0, sb, t1, invcnt, NN, HH);
    // 6. x_out = t1 @ lw + lb
    gemm128_kernel<F_BIAS><<<GB, 256>>>(t1, lw, HH, nullptr, nullptr, 0,
                                        lb, x_out, nullptr, NN, HH);
}

extern "C" void kernel_launch(void* const* d_in, const int* in_sizes, int n_in,
                              void* d_out, int out_size) {
    const float* x    = (const float*)d_in[0];
    const int*   ei   = (const int*)  d_in[1];
    const float* w    = (const float*)d_in[2];
    const float* pre_w1 = (const float*)d_in[3];
    const float* pre_b1 = (const float*)d_in[4];
    const float* cw0_1  = (const float*)d_in[5];
    const float* cw1_1  = (const float*)d_in[6];
    const float* cb_1   = (const float*)d_in[7];
    const float* sw_1   = (const float*)d_in[8];
    const float* sb_1   = (const float*)d_in[9];
    const float* lw_1   = (const float*)d_in[10];
    const float* lb_1   = (const float*)d_in[11];
    const float* pre_w2 = (const float*)d_in[12];
    const float* pre_b2 = (const float*)d_in[13];
    const float* cw0_2  = (const float*)d_in[14];
    const float* cw1_2  = (const float*)d_in[15];
    const float* cb_2   = (const float*)d_in[16];
    const float* sw_2   = (const float*)d_in[17];
    const float* sb_2   = (const float*)d_in[18];
    const float* lw_2   = (const float*)d_in[19];
    const float* lb_2   = (const float*)d_in[20];
    const float* cls_w  = (const float*)d_in[21];
    const float* cls_b  = (const float*)d_in[22];
    float* out = (float*)d_out;

    void *p_xh, *p_tx1, *p_s, *p_t1, *p_xc, *p_invcnt;
    cudaGetSymbolAddress(&p_xh,  g_xh);
    cudaGetSymbolAddress(&p_tx1, g_tx1);
    cudaGetSymbolAddress(&p_s,   g_s);
    cudaGetSymbolAddress(&p_t1,  g_t1);
    cudaGetSymbolAddress(&p_xc,  g_xc);
    cudaGetSymbolAddress(&p_invcnt, g_invcnt);
    float* xh  = (float*)p_xh;
    float* tx1 = (float*)p_tx1;
    float* s   = (float*)p_s;
    float* t1  = (float*)p_t1;
    float* xc  = (float*)p_xc;
    float* invcnt = (float*)p_invcnt;

    prep_zero_kernel<<<(NN + 255)/256, 256>>>();
    prep_edge_kernel<<<(NE + 255)/256, 256>>>(ei, w);
    prep_node_kernel<<<(NN + 255)/256, 256>>>();

    run_cell(x,  ei, w, pre_w1, pre_b1, cw0_1, cw1_1, cb_1, sw_1, sb_1, lw_1, lb_1,
             xh, tx1, s, t1, xc, invcnt, FIN);
    run_cell(xc, ei, w, pre_w2, pre_b2, cw0_2, cw1_2, cb_2, sw_2, sb_2, lw_2, lb_2,
             xh, tx1, s, t1, xc, invcnt, HH);

    gemm128_kernel<F_BIAS><<<(NN + 127)/128, 256>>>(xc, cls_w, HH, nullptr, nullptr, 0,
                                                    cls_b, out, nullptr, NN, CO);
    logsoftmax_kernel<<<(NN*32 + 255)/256, 256>>>(out);
}

// round 3
// speedup vs baseline: 2.2381x; 2.2381x over previous
#include <cuda_runtime.h>
#include <cuda_bf16.h>
#include <math.h>
#include <stdint.h>

#define NN   40000
#define NE   640000
#define FIN  512
#define HH   128
#define CO   40

// ---------------- scratch (device globals) ----------------
__device__ __align__(16) float g_xh [NN*HH];
__device__ __align__(16) float g_tx1[NN*HH];
__device__ __align__(16) float g_s  [NN*HH];
__device__ __align__(16) float g_t1 [NN*HH];
__device__ __align__(16) float g_xc [NN*HH];
__device__ float g_deg   [NN];
__device__ float g_dis   [NN];
__device__ float g_loopw [NN];
__device__ float g_invcnt[NN];

// ---------------- graph prep ----------------
__global__ void prep_zero_kernel() {
    int n = blockIdx.x * blockDim.x + threadIdx.x;
    if (n < NN) { g_deg[n] = 0.0f; g_loopw[n] = 1.0f; g_invcnt[n] = 0.0f; }
}

__global__ void prep_edge_kernel(const int* __restrict__ ei, const float* __restrict__ w) {
    int e = blockIdx.x * blockDim.x + threadIdx.x;
    if (e >= NE) return;
    int s = ei[e], d = ei[NE + e];
    float we = w[e];
    if (s != d) {
        atomicAdd(&g_deg[s], we);
        atomicAdd(&g_invcnt[d], 1.0f);
    } else {
        g_loopw[s] = we;
    }
}

__global__ void prep_node_kernel() {
    int n = blockIdx.x * blockDim.x + threadIdx.x;
    if (n >= NN) return;
    float dg = g_deg[n];
    g_dis[n]    = (dg > 0.0f) ? rsqrtf(dg) : 0.0f;
    g_invcnt[n] = 1.0f / (g_invcnt[n] + 1.0f);
}

// ---------------- per-cell init: tx1 = 0 ; s = loop_w * xh ----------------
__global__ void init_ts_kernel(const float4* __restrict__ xh,
                               float4* __restrict__ tx1, float4* __restrict__ s) {
    int i = blockIdx.x * blockDim.x + threadIdx.x;
    if (i >= NN * (HH/4)) return;
    int n = i >> 5;
    float lw = g_loopw[n];
    float4 v = xh[i];
    tx1[i] = make_float4(0.f, 0.f, 0.f, 0.f);
    s[i]   = make_float4(v.x*lw, v.y*lw, v.z*lw, v.w*lw);
}

// ---------------- fused edge scatter ----------------
__global__ __launch_bounds__(256)
void scatter_kernel(const int* __restrict__ ei, const float* __restrict__ w,
                    const float4* __restrict__ xh,
                    float4* __restrict__ tx1, float4* __restrict__ s) {
    int gw   = (blockIdx.x * blockDim.x + threadIdx.x) >> 5;
    int lane = threadIdx.x & 31;
    if (gw >= NE) return;
    int src = ei[gw], dst = ei[NE + gw];
    if (src == dst) return;
    float we   = w[gw];
    float coef = -g_dis[src] * we * g_dis[dst];
    float4 v = xh[src * 32 + lane];
    float4 a = make_float4(v.x*coef, v.y*coef, v.z*coef, v.w*coef);
    float4 b = make_float4(v.x*we,   v.y*we,   v.z*we,   v.w*we);
    atomicAdd(&tx1[dst * 32 + lane], a);
    atomicAdd(&s  [dst * 32 + lane], b);
}

// ---------------- TF32 tensor-core GEMM ----------------
// C[Nrows x M] = epi( A[Nrows x K] @ B[K x M] ),  M <= 128, K % 16 == 0
// Block tile 128x128, 8 warps as 2(M) x 4(N), warp tile 64x32,
// K-tile 16, double-buffered smem, mma.sync.m16n8k8 tf32.
#define F_BIAS       1
#define F_LEAKY      2
#define F_ADDC_PRE   4
#define F_ADDC_POST  8
#define F_ROWSCALE  16

__device__ __forceinline__ float tf32r(float x) {
    uint32_t u;
    asm("cvt.rna.tf32.f32 %0, %1;" : "=r"(u) : "f"(x));
    return __uint_as_float(u);
}

template<int FLAGS>
__global__ __launch_bounds__(256)
void gemm_tc_kernel(const float* __restrict__ A, const float* __restrict__ B,
                    const float* __restrict__ bias, float* __restrict__ C,
                    const float* __restrict__ rowscale, int Nrows, int K, int M) {
    __shared__ float As[2][16][136];   // [k][m], tf32 bits
    __shared__ float Bs[2][16][136];   // [k][n], tf32 bits

    const int tid   = threadIdx.x;
    const int r0    = blockIdx.x * 128;
    const int wid   = tid >> 5;
    const int lane  = tid & 31;
    const int grp   = lane >> 2;       // 0..7
    const int qid   = lane & 3;        // 0..3
    const int warpM = wid & 1;         // 2 M-warps
    const int warpN = wid >> 1;        // 4 N-warps

    float acc[4][4][4];
    #pragma unroll
    for (int mi = 0; mi < 4; mi++)
        #pragma unroll
        for (int ni = 0; ni < 4; ni++)
            #pragma unroll
            for (int r = 0; r < 4; r++) acc[mi][ni][r] = 0.0f;

    const int nt = K >> 4;

    auto load_tile = [&](int k0, int buf) {
        // A: 128 rows x 16 k, transposed store with tf32 convert
        #pragma unroll
        for (int i = 0; i < 2; i++) {
            int idx = tid + i * 256;           // 0..511
            int row = idx >> 2;
            int kc  = (idx & 3) << 2;
            int gr  = r0 + row;
            float4 v = make_float4(0.f, 0.f, 0.f, 0.f);
            if (gr < Nrows) v = *(const float4*)&A[(size_t)gr * K + k0 + kc];
            As[buf][kc+0][row] = tf32r(v.x);
            As[buf][kc+1][row] = tf32r(v.y);
            As[buf][kc+2][row] = tf32r(v.z);
            As[buf][kc+3][row] = tf32r(v.w);
        }
        // B: 16 k x up-to-128 cols
        #pragma unroll
        for (int i = 0; i < 2; i++) {
            int idx = tid + i * 256;           // 0..511
            int kr  = idx >> 5;
            int col = (idx & 31) << 2;
            float4 v = make_float4(0.f, 0.f, 0.f, 0.f);
            if (col < M) v = *(const float4*)&B[(size_t)(k0 + kr) * M + col];
            v.x = tf32r(v.x); v.y = tf32r(v.y); v.z = tf32r(v.z); v.w = tf32r(v.w);
            *(float4*)&Bs[buf][kr][col] = v;
        }
    };

    load_tile(0, 0);
    __syncthreads();

    int buf = 0;
    for (int t = 0; t < nt; t++) {
        if (t + 1 < nt) load_tile((t + 1) << 4, buf ^ 1);

        #pragma unroll
        for (int ks = 0; ks < 16; ks += 8) {
            uint32_t af[4][4];
            uint32_t bf[4][2];
            #pragma unroll
            for (int mi = 0; mi < 4; mi++) {
                int m = warpM * 64 + mi * 16 + grp;
                af[mi][0] = __float_as_uint(As[buf][ks + qid    ][m]);
                af[mi][1] = __float_as_uint(As[buf][ks + qid    ][m + 8]);
                af[mi][2] = __float_as_uint(As[buf][ks + qid + 4][m]);
                af[mi][3] = __float_as_uint(As[buf][ks + qid + 4][m + 8]);
            }
            #pragma unroll
            for (int ni = 0; ni < 4; ni++) {
                int n = warpN * 32 + ni * 8 + grp;
                bf[ni][0] = __float_as_uint(Bs[buf][ks + qid    ][n]);
                bf[ni][1] = __float_as_uint(Bs[buf][ks + qid + 4][n]);
            }
            #pragma unroll
            for (int mi = 0; mi < 4; mi++)
                #pragma unroll
                for (int ni = 0; ni < 4; ni++) {
                    asm volatile(
                        "mma.sync.aligned.m16n8k8.row.col.f32.tf32.tf32.f32 "
                        "{%0,%1,%2,%3}, {%4,%5,%6,%7}, {%8,%9}, {%0,%1,%2,%3};"
                        : "+f"(acc[mi][ni][0]), "+f"(acc[mi][ni][1]),
                          "+f"(acc[mi][ni][2]), "+f"(acc[mi][ni][3])
                        : "r"(af[mi][0]), "r"(af[mi][1]), "r"(af[mi][2]), "r"(af[mi][3]),
                          "r"(bf[ni][0]), "r"(bf[ni][1]));
                }
        }
        __syncthreads();
        buf ^= 1;
    }

    // epilogue: C-frag rows = grp, grp+8; cols = qid*2, qid*2+1
    #pragma unroll
    for (int mi = 0; mi < 4; mi++) {
        #pragma unroll
        for (int half = 0; half < 2; half++) {
            int row = r0 + warpM * 64 + mi * 16 + grp + half * 8;
            if (row >= Nrows) continue;
            float rs = (FLAGS & F_ROWSCALE) ? rowscale[row] : 1.0f;
            #pragma unroll
            for (int ni = 0; ni < 4; ni++) {
                int col = warpN * 32 + ni * 8 + qid * 2;
                if (col >= M) continue;
                size_t off = (size_t)row * M + col;
                float vx = acc[mi][ni][half * 2 + 0] * rs;
                float vy = acc[mi][ni][half * 2 + 1] * rs;
                if (FLAGS & F_BIAS)     { vx += bias[col]; vy += bias[col + 1]; }
                if (FLAGS & F_ADDC_PRE) { float2 c = *(const float2*)&C[off]; vx += c.x; vy += c.y; }
                if (FLAGS & F_LEAKY) {
                    vx = (vx > 0.f) ? vx : 0.01f * vx;
                    vy = (vy > 0.f) ? vy : 0.01f * vy;
                }
                if (FLAGS & F_ADDC_POST) { float2 c = *(const float2*)&C[off]; vx += c.x; vy += c.y; }
                *(float2*)&C[off] = make_float2(vx, vy);
            }
        }
    }
}

// ---------------- log_softmax over 40 cols, warp per row ----------------
__global__ __launch_bounds__(256)
void logsoftmax_kernel(float* __restrict__ out) {
    int row  = (blockIdx.x * blockDim.x + threadIdx.x) >> 5;
    int lane = threadIdx.x & 31;
    if (row >= NN) return;
    float* p = out + (size_t)row * CO;
    float v0 = p[lane];
    float v1 = (lane < CO - 32) ? p[32 + lane] : -3.4e38f;
    float m = fmaxf(v0, v1);
    #pragma unroll
    for (int o = 16; o > 0; o >>= 1) m = fmaxf(m, __shfl_xor_sync(0xffffffffu, m, o));
    float e = expf(v0 - m) + ((lane < CO - 32) ? expf(v1 - m) : 0.0f);
    #pragma unroll
    for (int o = 16; o > 0; o >>= 1) e += __shfl_xor_sync(0xffffffffu, e, o);
    float ls = m + logf(e);
    p[lane] = v0 - ls;
    if (lane < CO - 32) p[32 + lane] = v1 - ls;
}

// ---------------- launch ----------------
static void run_cell(const float* x_in, const int* ei, const float* w,
                     const float* pw, const float* pb,
                     const float* cw0, const float* cw1, const float* cb,
                     const float* sw, const float* sb,
                     const float* lw, const float* lb,
                     float* xh, float* tx1, float* s, float* t1, float* x_out,
                     float* invcnt, int Kin) {
    const int GB = (NN + 127) / 128;
    // 1. xh = x_in @ pw + pb
    gemm_tc_kernel<F_BIAS><<<GB, 256>>>(x_in, pw, pb, xh, nullptr, NN, Kin, HH);
    // 2. tx1 = 0 ; s = loop_w * xh
    init_ts_kernel<<<(NN*(HH/4) + 255)/256, 256>>>((const float4*)xh, (float4*)tx1, (float4*)s);
    // 3. fused scatter
    scatter_kernel<<<(NE*32 + 255)/256, 256>>>(ei, w, (const float4*)xh, (float4*)tx1, (float4*)s);
    // 4. t1 = xh @ cw0 + cb
    gemm_tc_kernel<F_BIAS><<<GB, 256>>>(xh, cw0, cb, t1, nullptr, NN, HH, HH);
    // 5. t1 = leaky(tx1 @ cw1 + t1)
    gemm_tc_kernel<F_ADDC_PRE | F_LEAKY><<<GB, 256>>>(tx1, cw1, nullptr, t1, nullptr, NN, HH, HH);
    // 6. t1 += leaky((s * invcnt_row) @ sw + sb)
    gemm_tc_kernel<F_ROWSCALE | F_BIAS | F_LEAKY | F_ADDC_POST><<<GB, 256>>>(
        s, sw, sb, t1, invcnt, NN, HH, HH);
    // 7. x_out = t1 @ lw + lb
    gemm_tc_kernel<F_BIAS><<<GB, 256>>>(t1, lw, lb, x_out, nullptr, NN, HH, HH);
}

extern "C" void kernel_launch(void* const* d_in, const int* in_sizes, int n_in,
                              void* d_out, int out_size) {
    const float* x    = (const float*)d_in[0];
    const int*   ei   = (const int*)  d_in[1];
    const float* w    = (const float*)d_in[2];
    const float* pre_w1 = (const float*)d_in[3];
    const float* pre_b1 = (const float*)d_in[4];
    const float* cw0_1  = (const float*)d_in[5];
    const float* cw1_1  = (const float*)d_in[6];
    const float* cb_1   = (const float*)d_in[7];
    const float* sw_1   = (const float*)d_in[8];
    const float* sb_1   = (const float*)d_in[9];
    const float* lw_1   = (const float*)d_in[10];
    const float* lb_1   = (const float*)d_in[11];
    const float* pre_w2 = (const float*)d_in[12];
    const float* pre_b2 = (const float*)d_in[13];
    const float* cw0_2  = (const float*)d_in[14];
    const float* cw1_2  = (const float*)d_in[15];
    const float* cb_2   = (const float*)d_in[16];
    const float* sw_2   = (const float*)d_in[17];
    const float* sb_2   = (const float*)d_in[18];
    const float* lw_2   = (const float*)d_in[19];
    const float* lb_2   = (const float*)d_in[20];
    const float* cls_w  = (const float*)d_in[21];
    const float* cls_b  = (const float*)d_in[22];
    float* out = (float*)d_out;

    void *p_xh, *p_tx1, *p_s, *p_t1, *p_xc, *p_invcnt;
    cudaGetSymbolAddress(&p_xh,  g_xh);
    cudaGetSymbolAddress(&p_tx1, g_tx1);
    cudaGetSymbolAddress(&p_s,   g_s);
    cudaGetSymbolAddress(&p_t1,  g_t1);
    cudaGetSymbolAddress(&p_xc,  g_xc);
    cudaGetSymbolAddress(&p_invcnt, g_invcnt);
    float* xh  = (float*)p_xh;
    float* tx1 = (float*)p_tx1;
    float* s   = (float*)p_s;
    float* t1  = (float*)p_t1;
    float* xc  = (float*)p_xc;
    float* invcnt = (float*)p_invcnt;

    prep_zero_kernel<<<(NN + 255)/256, 256>>>();
    prep_edge_kernel<<<(NE + 255)/256, 256>>>(ei, w);
    prep_node_kernel<<<(NN + 255)/256, 256>>>();

    run_cell(x,  ei, w, pre_w1, pre_b1, cw0_1, cw1_1, cb_1, sw_1, sb_1, lw_1, lb_1,
             xh, tx1, s, t1, xc, invcnt, FIN);
    run_cell(xc, ei, w, pre_w2, pre_b2, cw0_2, cw1_2, cb_2, sw_2, sb_2, lw_2, lb_2,
             xh, tx1, s, t1, xc, invcnt, HH);

    gemm_tc_kernel<F_BIAS><<<(NN + 127)/128, 256>>>(xc, cls_w, cls_b, out, nullptr, NN, HH, CO);
    logsoftmax_kernel<<<(NN*32 + 255)/256, 256>>>(out);
}

// round 4
// speedup vs baseline: 2.7179x; 1.2144x over previous
#include <cuda_runtime.h>
#include <cuda_bf16.h>
#include <math.h>
#include <stdint.h>

#define NN   40000
#define NE   640000
#define FIN  512
#define HH   128
#define CO   40

// ---------------- scratch (device globals) ----------------
__device__ __align__(16) float g_xh [NN*HH];
__device__ __align__(16) float g_tx1[NN*HH];
__device__ __align__(16) float g_s  [NN*HH];
__device__ __align__(16) float g_t1 [NN*HH];
__device__ __align__(16) float g_xc [NN*HH];
__device__ float g_deg   [NN];
__device__ float g_dis   [NN];
__device__ float g_loopw [NN];
__device__ float g_invcnt[NN];
__device__ int   g_cnt   [NN];
__device__ int   g_cursor[NN];
__device__ int   g_rowptr[NN + 1];
__device__ __align__(16) int4 g_emeta[NE];   // {src, w(bits), coef(bits), 0} sorted by dst

// ---------------- graph prep ----------------
__global__ void prep_zero_kernel() {
    int n = blockIdx.x * blockDim.x + threadIdx.x;
    if (n < NN) { g_deg[n] = 0.0f; g_loopw[n] = 1.0f; g_cnt[n] = 0; g_cursor[n] = 0; }
}

__global__ void prep_edge_kernel(const int* __restrict__ ei, const float* __restrict__ w) {
    int e = blockIdx.x * blockDim.x + threadIdx.x;
    if (e >= NE) return;
    int s = ei[e], d = ei[NE + e];
    float we = w[e];
    if (s != d) {
        atomicAdd(&g_deg[s], we);
        atomicAdd(&g_cnt[d], 1);
    } else {
        g_loopw[s] = we;
    }
}

__global__ void prep_node_kernel() {
    int n = blockIdx.x * blockDim.x + threadIdx.x;
    if (n >= NN) return;
    float dg = g_deg[n];
    g_dis[n]    = (dg > 0.0f) ? rsqrtf(dg) : 0.0f;
    g_invcnt[n] = 1.0f / ((float)g_cnt[n] + 1.0f);
}

// ---------------- exclusive scan of g_cnt -> g_rowptr (single block) ----------------
__global__ __launch_bounds__(1024)
void scan_kernel() {
    __shared__ int ssum[1024];
    const int T  = 1024;
    const int CH = (NN + T - 1) / T;     // 40
    int t    = threadIdx.x;
    int base = t * CH;
    int local = 0;
    for (int i = 0; i < CH; i++) {
        int idx = base + i;
        if (idx < NN) local += g_cnt[idx];
    }
    ssum[t] = local;
    __syncthreads();
    // inclusive Hillis-Steele scan over 1024 partials
    for (int off = 1; off < T; off <<= 1) {
        int v = (t >= off) ? ssum[t - off] : 0;
        __syncthreads();
        ssum[t] += v;
        __syncthreads();
    }
    int run = ssum[t] - local;           // exclusive prefix of this chunk
    for (int i = 0; i < CH; i++) {
        int idx = base + i;
        if (idx < NN) { g_rowptr[idx] = run; run += g_cnt[idx]; }
    }
    if (t == T - 1) g_rowptr[NN] = run;  // last chunks empty -> run == total
}

// ---------------- fill CSR with packed edge meta ----------------
__global__ void fill_kernel(const int* __restrict__ ei, const float* __restrict__ w) {
    int e = blockIdx.x * blockDim.x + threadIdx.x;
    if (e >= NE) return;
    int s = ei[e], d = ei[NE + e];
    if (s == d) return;
    float we   = w[e];
    float coef = -g_dis[s] * we * g_dis[d];
    int pos = g_rowptr[d] + atomicAdd(&g_cursor[d], 1);
    g_emeta[pos] = make_int4(s, __float_as_int(we), __float_as_int(coef), 0);
}

// ---------------- CSR gather-reduce: warp per node ----------------
// tx1[n] = sum coef*xh[src] ; s[n] = invcnt[n] * (loopw[n]*xh[n] + sum w*xh[src])
__global__ __launch_bounds__(256)
void aggregate_kernel(const float4* __restrict__ xh,
                      float4* __restrict__ tx1, float4* __restrict__ s) {
    int n    = (blockIdx.x * blockDim.x + threadIdx.x) >> 5;
    int lane = threadIdx.x & 31;
    if (n >= NN) return;
    int beg = g_rowptr[n], end = g_rowptr[n + 1];

    float lw = g_loopw[n];
    float4 xv = xh[n * 32 + lane];
    float4 a = make_float4(0.f, 0.f, 0.f, 0.f);
    float4 b = make_float4(lw * xv.x, lw * xv.y, lw * xv.z, lw * xv.w);

    for (int e = beg; e < end; e++) {
        int4 m = g_emeta[e];                       // broadcast across warp
        float we = __int_as_float(m.y);
        float cf = __int_as_float(m.z);
        float4 v = xh[m.x * 32 + lane];
        a.x += cf * v.x; a.y += cf * v.y; a.z += cf * v.z; a.w += cf * v.w;
        b.x += we * v.x; b.y += we * v.y; b.z += we * v.z; b.w += we * v.w;
    }
    float ic = g_invcnt[n];
    tx1[n * 32 + lane] = a;
    s  [n * 32 + lane] = make_float4(b.x * ic, b.y * ic, b.z * ic, b.w * ic);
}

// ---------------- TF32 tensor-core GEMM ----------------
#define F_BIAS       1
#define F_LEAKY      2
#define F_ADDC_PRE   4
#define F_ADDC_POST  8

__device__ __forceinline__ float tf32r(float x) {
    uint32_t u;
    asm("cvt.rna.tf32.f32 %0, %1;" : "=r"(u) : "f"(x));
    return __uint_as_float(u);
}

template<int FLAGS>
__global__ __launch_bounds__(256)
void gemm_tc_kernel(const float* __restrict__ A, const float* __restrict__ B,
                    const float* __restrict__ bias, float* __restrict__ C,
                    int Nrows, int K, int M) {
    __shared__ float As[2][16][136];
    __shared__ float Bs[2][16][136];

    const int tid   = threadIdx.x;
    const int r0    = blockIdx.x * 128;
    const int wid   = tid >> 5;
    const int lane  = tid & 31;
    const int grp   = lane >> 2;
    const int qid   = lane & 3;
    const int warpM = wid & 1;
    const int warpN = wid >> 1;

    float acc[4][4][4];
    #pragma unroll
    for (int mi = 0; mi < 4; mi++)
        #pragma unroll
        for (int ni = 0; ni < 4; ni++)
            #pragma unroll
            for (int r = 0; r < 4; r++) acc[mi][ni][r] = 0.0f;

    const int nt = K >> 4;

    auto load_tile = [&](int k0, int buf) {
        #pragma unroll
        for (int i = 0; i < 2; i++) {
            int idx = tid + i * 256;
            int row = idx >> 2;
            int kc  = (idx & 3) << 2;
            int gr  = r0 + row;
            float4 v = make_float4(0.f, 0.f, 0.f, 0.f);
            if (gr < Nrows) v = *(const float4*)&A[(size_t)gr * K + k0 + kc];
            As[buf][kc+0][row] = tf32r(v.x);
            As[buf][kc+1][row] = tf32r(v.y);
            As[buf][kc+2][row] = tf32r(v.z);
            As[buf][kc+3][row] = tf32r(v.w);
        }
        #pragma unroll
        for (int i = 0; i < 2; i++) {
            int idx = tid + i * 256;
            int kr  = idx >> 5;
            int col = (idx & 31) << 2;
            float4 v = make_float4(0.f, 0.f, 0.f, 0.f);
            if (col < M) v = *(const float4*)&B[(size_t)(k0 + kr) * M + col];
            v.x = tf32r(v.x); v.y = tf32r(v.y); v.z = tf32r(v.z); v.w = tf32r(v.w);
            *(float4*)&Bs[buf][kr][col] = v;
        }
    };

    load_tile(0, 0);
    __syncthreads();

    int buf = 0;
    for (int t = 0; t < nt; t++) {
        if (t + 1 < nt) load_tile((t + 1) << 4, buf ^ 1);

        #pragma unroll
        for (int ks = 0; ks < 16; ks += 8) {
            uint32_t af[4][4];
            uint32_t bf[4][2];
            #pragma unroll
            for (int mi = 0; mi < 4; mi++) {
                int m = warpM * 64 + mi * 16 + grp;
                af[mi][0] = __float_as_uint(As[buf][ks + qid    ][m]);
                af[mi][1] = __float_as_uint(As[buf][ks + qid    ][m + 8]);
                af[mi][2] = __float_as_uint(As[buf][ks + qid + 4][m]);
                af[mi][3] = __float_as_uint(As[buf][ks + qid + 4][m + 8]);
            }
            #pragma unroll
            for (int ni = 0; ni < 4; ni++) {
                int n = warpN * 32 + ni * 8 + grp;
                bf[ni][0] = __float_as_uint(Bs[buf][ks + qid    ][n]);
                bf[ni][1] = __float_as_uint(Bs[buf][ks + qid + 4][n]);
            }
            #pragma unroll
            for (int mi = 0; mi < 4; mi++)
                #pragma unroll
                for (int ni = 0; ni < 4; ni++) {
                    asm volatile(
                        "mma.sync.aligned.m16n8k8.row.col.f32.tf32.tf32.f32 "
                        "{%0,%1,%2,%3}, {%4,%5,%6,%7}, {%8,%9}, {%0,%1,%2,%3};"
                        : "+f"(acc[mi][ni][0]), "+f"(acc[mi][ni][1]),
                          "+f"(acc[mi][ni][2]), "+f"(acc[mi][ni][3])
                        : "r"(af[mi][0]), "r"(af[mi][1]), "r"(af[mi][2]), "r"(af[mi][3]),
                          "r"(bf[ni][0]), "r"(bf[ni][1]));
                }
        }
        __syncthreads();
        buf ^= 1;
    }

    #pragma unroll
    for (int mi = 0; mi < 4; mi++) {
        #pragma unroll
        for (int half = 0; half < 2; half++) {
            int row = r0 + warpM * 64 + mi * 16 + grp + half * 8;
            if (row >= Nrows) continue;
            #pragma unroll
            for (int ni = 0; ni < 4; ni++) {
                int col = warpN * 32 + ni * 8 + qid * 2;
                if (col >= M) continue;
                size_t off = (size_t)row * M + col;
                float vx = acc[mi][ni][half * 2 + 0];
                float vy = acc[mi][ni][half * 2 + 1];
                if (FLAGS & F_BIAS)     { vx += bias[col]; vy += bias[col + 1]; }
                if (FLAGS & F_ADDC_PRE) { float2 c = *(const float2*)&C[off]; vx += c.x; vy += c.y; }
                if (FLAGS & F_LEAKY) {
                    vx = (vx > 0.f) ? vx : 0.01f * vx;
                    vy = (vy > 0.f) ? vy : 0.01f * vy;
                }
                if (FLAGS & F_ADDC_POST) { float2 c = *(const float2*)&C[off]; vx += c.x; vy += c.y; }
                *(float2*)&C[off] = make_float2(vx, vy);
            }
        }
    }
}

// ---------------- log_softmax ----------------
__global__ __launch_bounds__(256)
void logsoftmax_kernel(float* __restrict__ out) {
    int row  = (blockIdx.x * blockDim.x + threadIdx.x) >> 5;
    int lane = threadIdx.x & 31;
    if (row >= NN) return;
    float* p = out + (size_t)row * CO;
    float v0 = p[lane];
    float v1 = (lane < CO - 32) ? p[32 + lane] : -3.4e38f;
    float m = fmaxf(v0, v1);
    #pragma unroll
    for (int o = 16; o > 0; o >>= 1) m = fmaxf(m, __shfl_xor_sync(0xffffffffu, m, o));
    float e = expf(v0 - m) + ((lane < CO - 32) ? expf(v1 - m) : 0.0f);
    #pragma unroll
    for (int o = 16; o > 0; o >>= 1) e += __shfl_xor_sync(0xffffffffu, e, o);
    float ls = m + logf(e);
    p[lane] = v0 - ls;
    if (lane < CO - 32) p[32 + lane] = v1 - ls;
}

// ---------------- launch ----------------
static void run_cell(const float* x_in,
                     const float* pw, const float* pb,
                     const float* cw0, const float* cw1, const float* cb,
                     const float* sw, const float* sb,
                     const float* lw, const float* lb,
                     float* xh, float* tx1, float* s, float* t1, float* x_out,
                     int Kin) {
    const int GB = (NN + 127) / 128;
    // 1. xh = x_in @ pw + pb
    gemm_tc_kernel<F_BIAS><<<GB, 256>>>(x_in, pw, pb, xh, NN, Kin, HH);
    // 2. CSR gather-reduce: tx1, s (incl. loop term and 1/cnt)
    aggregate_kernel<<<(NN * 32 + 255) / 256, 256>>>((const float4*)xh, (float4*)tx1, (float4*)s);
    // 3. t1 = xh @ cw0 + cb
    gemm_tc_kernel<F_BIAS><<<GB, 256>>>(xh, cw0, cb, t1, NN, HH, HH);
    // 4. t1 = leaky(tx1 @ cw1 + t1)
    gemm_tc_kernel<F_ADDC_PRE | F_LEAKY><<<GB, 256>>>(tx1, cw1, nullptr, t1, NN, HH, HH);
    // 5. t1 += leaky(s @ sw + sb)
    gemm_tc_kernel<F_BIAS | F_LEAKY | F_ADDC_POST><<<GB, 256>>>(s, sw, sb, t1, NN, HH, HH);
    // 6. x_out = t1 @ lw + lb
    gemm_tc_kernel<F_BIAS><<<GB, 256>>>(t1, lw, lb, x_out, NN, HH, HH);
}

extern "C" void kernel_launch(void* const* d_in, const int* in_sizes, int n_in,
                              void* d_out, int out_size) {
    const float* x    = (const float*)d_in[0];
    const int*   ei   = (const int*)  d_in[1];
    const float* w    = (const float*)d_in[2];
    const float* pre_w1 = (const float*)d_in[3];
    const float* pre_b1 = (const float*)d_in[4];
    const float* cw0_1  = (const float*)d_in[5];
    const float* cw1_1  = (const float*)d_in[6];
    const float* cb_1   = (const float*)d_in[7];
    const float* sw_1   = (const float*)d_in[8];
    const float* sb_1   = (const float*)d_in[9];
    const float* lw_1   = (const float*)d_in[10];
    const float* lb_1   = (const float*)d_in[11];
    const float* pre_w2 = (const float*)d_in[12];
    const float* pre_b2 = (const float*)d_in[13];
    const float* cw0_2  = (const float*)d_in[14];
    const float* cw1_2  = (const float*)d_in[15];
    const float* cb_2   = (const float*)d_in[16];
    const float* sw_2   = (const float*)d_in[17];
    const float* sb_2   = (const float*)d_in[18];
    const float* lw_2   = (const float*)d_in[19];
    const float* lb_2   = (const float*)d_in[20];
    const float* cls_w  = (const float*)d_in[21];
    const float* cls_b  = (const float*)d_in[22];
    float* out = (float*)d_out;

    void *p_xh, *p_tx1, *p_s, *p_t1, *p_xc;
    cudaGetSymbolAddress(&p_xh,  g_xh);
    cudaGetSymbolAddress(&p_tx1, g_tx1);
    cudaGetSymbolAddress(&p_s,   g_s);
    cudaGetSymbolAddress(&p_t1,  g_t1);
    cudaGetSymbolAddress(&p_xc,  g_xc);
    float* xh  = (float*)p_xh;
    float* tx1 = (float*)p_tx1;
    float* s   = (float*)p_s;
    float* t1  = (float*)p_t1;
    float* xc  = (float*)p_xc;

    // graph prep + CSR build (once per launch; reused by both cells)
    prep_zero_kernel<<<(NN + 255)/256, 256>>>();
    prep_edge_kernel<<<(NE + 255)/256, 256>>>(ei, w);
    prep_node_kernel<<<(NN + 255)/256, 256>>>();
    scan_kernel<<<1, 1024>>>();
    fill_kernel<<<(NE + 255)/256, 256>>>(ei, w);

    run_cell(x,  pre_w1, pre_b1, cw0_1, cw1_1, cb_1, sw_1, sb_1, lw_1, lb_1,
             xh, tx1, s, t1, xc, FIN);
    run_cell(xc, pre_w2, pre_b2, cw0_2, cw1_2, cb_2, sw_2, sb_2, lw_2, lb_2,
             xh, tx1, s, t1, xc, HH);

    gemm_tc_kernel<F_BIAS><<<(NN + 127)/128, 256>>>(xc, cls_w, cls_b, out, NN, HH, CO);
    logsoftmax_kernel<<<(NN*32 + 255)/256, 256>>>(out);
}

// round 5
// speedup vs baseline: 2.8539x; 1.0501x over previous
#include <cuda_runtime.h>
#include <cuda_bf16.h>
#include <math.h>
#include <stdint.h>

#define NN   40000
#define NE   640000
#define FIN  512
#define HH   128
#define CO   40

// ---------------- scratch (device globals) ----------------
__device__ __align__(16) float g_xh [NN*HH];
__device__ __align__(16) float g_tx1[NN*HH];
__device__ __align__(16) float g_s  [NN*HH];
__device__ __align__(16) float g_t1 [NN*HH];
__device__ __align__(16) float g_xc [NN*HH];
__device__ float g_deg   [NN];
__device__ float g_dis   [NN];
__device__ float g_loopw [NN];
__device__ float g_invcnt[NN];
__device__ __align__(16) int g_cnt   [NN + 64];
__device__ int   g_cursor[NN];
__device__ int   g_rowptr[NN + 1];
__device__ __align__(16) int4 g_emeta[NE];   // {src, w(bits), coef(bits), 0} sorted by dst

// ---------------- graph prep ----------------
__global__ void prep_zero_kernel() {
    int n = blockIdx.x * blockDim.x + threadIdx.x;
    if (n < NN) { g_deg[n] = 0.0f; g_loopw[n] = 1.0f; g_cnt[n] = 0; g_cursor[n] = 0; }
}

__global__ void prep_edge_kernel(const int* __restrict__ ei, const float* __restrict__ w) {
    int e = blockIdx.x * blockDim.x + threadIdx.x;
    if (e >= NE) return;
    int s = ei[e], d = ei[NE + e];
    float we = w[e];
    if (s != d) {
        atomicAdd(&g_deg[s], we);
        atomicAdd(&g_cnt[d], 1);
    } else {
        g_loopw[s] = we;
    }
}

__global__ void prep_node_kernel() {
    int n = blockIdx.x * blockDim.x + threadIdx.x;
    if (n >= NN) return;
    float dg = g_deg[n];
    g_dis[n]    = (dg > 0.0f) ? rsqrtf(dg) : 0.0f;
    g_invcnt[n] = 1.0f / ((float)g_cnt[n] + 1.0f);
}

// ---------------- exclusive scan of g_cnt -> g_rowptr (single block, warp-scan) ----------------
__global__ __launch_bounds__(1024)
void scan_kernel() {
    __shared__ int swarp[32];
    const int T  = 1024;
    const int CH = 40;                    // covers 40960 >= NN
    int t    = threadIdx.x;
    int wid  = t >> 5;
    int lane = t & 31;
    int base = t * CH;

    // local sum via int4 loads (base*4 bytes is 160B-aligned)
    int local = 0;
    #pragma unroll
    for (int i = 0; i < CH / 4; i++) {
        int idx = base + i * 4;
        if (idx < NN) {
            int4 v = *(const int4*)&g_cnt[idx];   // g_cnt padded past NN with zeros? (zeroed below NN only)
            // guard tail elements
            local += (idx + 0 < NN ? v.x : 0) + (idx + 1 < NN ? v.y : 0)
                   + (idx + 2 < NN ? v.z : 0) + (idx + 3 < NN ? v.w : 0);
        }
    }
    // warp inclusive scan
    int incl = local;
    #pragma unroll
    for (int off = 1; off < 32; off <<= 1) {
        int v = __shfl_up_sync(0xffffffffu, incl, off);
        if (lane >= off) incl += v;
    }
    if (lane == 31) swarp[wid] = incl;
    __syncthreads();
    if (wid == 0) {
        int v = swarp[lane];
        int iv = v;
        #pragma unroll
        for (int off = 1; off < 32; off <<= 1) {
            int u = __shfl_up_sync(0xffffffffu, iv, off);
            if (lane >= off) iv += u;
        }
        swarp[lane] = iv - v;              // exclusive warp offsets
    }
    __syncthreads();
    int run = swarp[wid] + incl - local;   // exclusive prefix for this thread
    #pragma unroll 4
    for (int i = 0; i < CH; i++) {
        int idx = base + i;
        if (idx < NN) { g_rowptr[idx] = run; run += g_cnt[idx]; }
    }
    if (base <= NN && NN < base + CH) g_rowptr[NN] = run;
}

// ---------------- fill CSR with packed edge meta ----------------
__global__ void fill_kernel(const int* __restrict__ ei, const float* __restrict__ w) {
    int e = blockIdx.x * blockDim.x + threadIdx.x;
    if (e >= NE) return;
    int s = ei[e], d = ei[NE + e];
    if (s == d) return;
    float we   = w[e];
    float coef = -g_dis[s] * we * g_dis[d];
    int pos = g_rowptr[d] + atomicAdd(&g_cursor[d], 1);
    g_emeta[pos] = make_int4(s, __float_as_int(we), __float_as_int(coef), 0);
}

// ---------------- CSR gather-reduce: warp per node ----------------
__global__ __launch_bounds__(256)
void aggregate_kernel(const float4* __restrict__ xh,
                      float4* __restrict__ tx1, float4* __restrict__ s) {
    int n    = (blockIdx.x * blockDim.x + threadIdx.x) >> 5;
    int lane = threadIdx.x & 31;
    if (n >= NN) return;
    int beg = g_rowptr[n], end = g_rowptr[n + 1];

    float lw = g_loopw[n];
    float4 xv = xh[n * 32 + lane];
    float4 a = make_float4(0.f, 0.f, 0.f, 0.f);
    float4 b = make_float4(lw * xv.x, lw * xv.y, lw * xv.z, lw * xv.w);

    int e = beg;
    // unrolled-by-4 main loop for gather MLP
    for (; e + 4 <= end; e += 4) {
        int4 m0 = g_emeta[e+0], m1 = g_emeta[e+1], m2 = g_emeta[e+2], m3 = g_emeta[e+3];
        float4 v0 = xh[m0.x * 32 + lane];
        float4 v1 = xh[m1.x * 32 + lane];
        float4 v2 = xh[m2.x * 32 + lane];
        float4 v3 = xh[m3.x * 32 + lane];
        float w0 = __int_as_float(m0.y), c0 = __int_as_float(m0.z);
        float w1 = __int_as_float(m1.y), c1 = __int_as_float(m1.z);
        float w2 = __int_as_float(m2.y), c2 = __int_as_float(m2.z);
        float w3 = __int_as_float(m3.y), c3 = __int_as_float(m3.z);
        a.x += c0*v0.x + c1*v1.x + c2*v2.x + c3*v3.x;
        a.y += c0*v0.y + c1*v1.y + c2*v2.y + c3*v3.y;
        a.z += c0*v0.z + c1*v1.z + c2*v2.z + c3*v3.z;
        a.w += c0*v0.w + c1*v1.w + c2*v2.w + c3*v3.w;
        b.x += w0*v0.x + w1*v1.x + w2*v2.x + w3*v3.x;
        b.y += w0*v0.y + w1*v1.y + w2*v2.y + w3*v3.y;
        b.z += w0*v0.z + w1*v1.z + w2*v2.z + w3*v3.z;
        b.w += w0*v0.w + w1*v1.w + w2*v2.w + w3*v3.w;
    }
    for (; e < end; e++) {
        int4 m = g_emeta[e];
        float we = __int_as_float(m.y);
        float cf = __int_as_float(m.z);
        float4 v = xh[m.x * 32 + lane];
        a.x += cf * v.x; a.y += cf * v.y; a.z += cf * v.z; a.w += cf * v.w;
        b.x += we * v.x; b.y += we * v.y; b.z += we * v.z; b.w += we * v.w;
    }
    float ic = g_invcnt[n];
    tx1[n * 32 + lane] = a;
    s  [n * 32 + lane] = make_float4(b.x * ic, b.y * ic, b.z * ic, b.w * ic);
}

// ---------------- TF32 tensor-core GEMM (optional 2-segment K) ----------------
#define F_BIAS       1
#define F_LEAKY      2
#define F_ADDC_PRE   4
#define F_ADDC_POST  8

__device__ __forceinline__ float tf32r(float x) {
    uint32_t u;
    asm("cvt.rna.tf32.f32 %0, %1;" : "=r"(u) : "f"(x));
    return __uint_as_float(u);
}

template<int FLAGS>
__global__ __launch_bounds__(256)
void gemm_tc_kernel(const float* __restrict__ A1, const float* __restrict__ B1, int K1,
                    const float* __restrict__ A2, const float* __restrict__ B2, int K2,
                    const float* __restrict__ bias, float* __restrict__ C,
                    int Nrows, int M) {
    __shared__ float As[2][16][136];
    __shared__ float Bs[2][16][136];

    const int tid   = threadIdx.x;
    const int r0    = blockIdx.x * 128;
    const int wid   = tid >> 5;
    const int lane  = tid & 31;
    const int grp   = lane >> 2;
    const int qid   = lane & 3;
    const int warpM = wid & 1;
    const int warpN = wid >> 1;

    float acc[4][4][4];
    #pragma unroll
    for (int mi = 0; mi < 4; mi++)
        #pragma unroll
        for (int ni = 0; ni < 4; ni++)
            #pragma unroll
            for (int r = 0; r < 4; r++) acc[mi][ni][r] = 0.0f;

    const int nt = (K1 + K2) >> 4;

    auto load_tile = [&](int t, int buf) {
        int k0 = t << 4;
        const float* A; const float* B; int kk0; int Kld;
        if (k0 < K1) { A = A1; B = B1; kk0 = k0;      Kld = K1; }
        else         { A = A2; B = B2; kk0 = k0 - K1; Kld = K2; }
        #pragma unroll
        for (int i = 0; i < 2; i++) {
            int idx = tid + i * 256;
            int row = idx >> 2;
            int kc  = (idx & 3) << 2;
            int gr  = r0 + row;
            float4 v = make_float4(0.f, 0.f, 0.f, 0.f);
            if (gr < Nrows) v = *(const float4*)&A[(size_t)gr * Kld + kk0 + kc];
            As[buf][kc+0][row] = tf32r(v.x);
            As[buf][kc+1][row] = tf32r(v.y);
            As[buf][kc+2][row] = tf32r(v.z);
            As[buf][kc+3][row] = tf32r(v.w);
        }
        #pragma unroll
        for (int i = 0; i < 2; i++) {
            int idx = tid + i * 256;
            int kr  = idx >> 5;
            int col = (idx & 31) << 2;
            float4 v = make_float4(0.f, 0.f, 0.f, 0.f);
            if (col < M) v = *(const float4*)&B[(size_t)(kk0 + kr) * M + col];
            v.x = tf32r(v.x); v.y = tf32r(v.y); v.z = tf32r(v.z); v.w = tf32r(v.w);
            *(float4*)&Bs[buf][kr][col] = v;
        }
    };

    load_tile(0, 0);
    __syncthreads();

    int buf = 0;
    for (int t = 0; t < nt; t++) {
        if (t + 1 < nt) load_tile(t + 1, buf ^ 1);

        #pragma unroll
        for (int ks = 0; ks < 16; ks += 8) {
            uint32_t af[4][4];
            uint32_t bf[4][2];
            #pragma unroll
            for (int mi = 0; mi < 4; mi++) {
                int m = warpM * 64 + mi * 16 + grp;
                af[mi][0] = __float_as_uint(As[buf][ks + qid    ][m]);
                af[mi][1] = __float_as_uint(As[buf][ks + qid    ][m + 8]);
                af[mi][2] = __float_as_uint(As[buf][ks + qid + 4][m]);
                af[mi][3] = __float_as_uint(As[buf][ks + qid + 4][m + 8]);
            }
            #pragma unroll
            for (int ni = 0; ni < 4; ni++) {
                int n = warpN * 32 + ni * 8 + grp;
                bf[ni][0] = __float_as_uint(Bs[buf][ks + qid    ][n]);
                bf[ni][1] = __float_as_uint(Bs[buf][ks + qid + 4][n]);
            }
            #pragma unroll
            for (int mi = 0; mi < 4; mi++)
                #pragma unroll
                for (int ni = 0; ni < 4; ni++) {
                    asm volatile(
                        "mma.sync.aligned.m16n8k8.row.col.f32.tf32.tf32.f32 "
                        "{%0,%1,%2,%3}, {%4,%5,%6,%7}, {%8,%9}, {%0,%1,%2,%3};"
                        : "+f"(acc[mi][ni][0]), "+f"(acc[mi][ni][1]),
                          "+f"(acc[mi][ni][2]), "+f"(acc[mi][ni][3])
                        : "r"(af[mi][0]), "r"(af[mi][1]), "r"(af[mi][2]), "r"(af[mi][3]),
                          "r"(bf[ni][0]), "r"(bf[ni][1]));
                }
        }
        __syncthreads();
        buf ^= 1;
    }

    #pragma unroll
    for (int mi = 0; mi < 4; mi++) {
        #pragma unroll
        for (int half = 0; half < 2; half++) {
            int row = r0 + warpM * 64 + mi * 16 + grp + half * 8;
            if (row >= Nrows) continue;
            #pragma unroll
            for (int ni = 0; ni < 4; ni++) {
                int col = warpN * 32 + ni * 8 + qid * 2;
                if (col >= M) continue;
                size_t off = (size_t)row * M + col;
                float vx = acc[mi][ni][half * 2 + 0];
                float vy = acc[mi][ni][half * 2 + 1];
                if (FLAGS & F_BIAS)     { vx += bias[col]; vy += bias[col + 1]; }
                if (FLAGS & F_ADDC_PRE) { float2 c = *(const float2*)&C[off]; vx += c.x; vy += c.y; }
                if (FLAGS & F_LEAKY) {
                    vx = (vx > 0.f) ? vx : 0.01f * vx;
                    vy = (vy > 0.f) ? vy : 0.01f * vy;
                }
                if (FLAGS & F_ADDC_POST) { float2 c = *(const float2*)&C[off]; vx += c.x; vy += c.y; }
                *(float2*)&C[off] = make_float2(vx, vy);
            }
        }
    }
}

// ---------------- log_softmax ----------------
__global__ __launch_bounds__(256)
void logsoftmax_kernel(float* __restrict__ out) {
    int row  = (blockIdx.x * blockDim.x + threadIdx.x) >> 5;
    int lane = threadIdx.x & 31;
    if (row >= NN) return;
    float* p = out + (size_t)row * CO;
    float v0 = p[lane];
    float v1 = (lane < CO - 32) ? p[32 + lane] : -3.4e38f;
    float m = fmaxf(v0, v1);
    #pragma unroll
    for (int o = 16; o > 0; o >>= 1) m = fmaxf(m, __shfl_xor_sync(0xffffffffu, m, o));
    float e = expf(v0 - m) + ((lane < CO - 32) ? expf(v1 - m) : 0.0f);
    #pragma unroll
    for (int o = 16; o > 0; o >>= 1) e += __shfl_xor_sync(0xffffffffu, e, o);
    float ls = m + logf(e);
    p[lane] = v0 - ls;
    if (lane < CO - 32) p[32 + lane] = v1 - ls;
}

// ---------------- launch ----------------
static void run_cell(const float* x_in,
                     const float* pw, const float* pb,
                     const float* cw0, const float* cw1, const float* cb,
                     const float* sw, const float* sb,
                     const float* lw, const float* lb,
                     float* xh, float* tx1, float* s, float* t1, float* x_out,
                     int Kin) {
    const int GB = (NN + 127) / 128;
    // 1. xh = x_in @ pw + pb
    gemm_tc_kernel<F_BIAS><<<GB, 256>>>(x_in, pw, Kin, nullptr, nullptr, 0, pb, xh, NN, HH);
    // 2. CSR gather-reduce: tx1, s
    aggregate_kernel<<<(NN * 32 + 255) / 256, 256>>>((const float4*)xh, (float4*)tx1, (float4*)s);
    // 3. t1 = leaky(xh @ cw0 + tx1 @ cw1 + cb)    [fused two-segment GEMM]
    gemm_tc_kernel<F_BIAS | F_LEAKY><<<GB, 256>>>(xh, cw0, HH, tx1, cw1, HH, cb, t1, NN, HH);
    // 4. t1 += leaky(s @ sw + sb)
    gemm_tc_kernel<F_BIAS | F_LEAKY | F_ADDC_POST><<<GB, 256>>>(s, sw, HH, nullptr, nullptr, 0, sb, t1, NN, HH);
    // 5. x_out = t1 @ lw + lb
    gemm_tc_kernel<F_BIAS><<<GB, 256>>>(t1, lw, HH, nullptr, nullptr, 0, lb, x_out, NN, HH);
}

extern "C" void kernel_launch(void* const* d_in, const int* in_sizes, int n_in,
                              void* d_out, int out_size) {
    const float* x    = (const float*)d_in[0];
    const int*   ei   = (const int*)  d_in[1];
    const float* w    = (const float*)d_in[2];
    const float* pre_w1 = (const float*)d_in[3];
    const float* pre_b1 = (const float*)d_in[4];
    const float* cw0_1  = (const float*)d_in[5];
    const float* cw1_1  = (const float*)d_in[6];
    const float* cb_1   = (const float*)d_in[7];
    const float* sw_1   = (const float*)d_in[8];
    const float* sb_1   = (const float*)d_in[9];
    const float* lw_1   = (const float*)d_in[10];
    const float* lb_1   = (const float*)d_in[11];
    const float* pre_w2 = (const float*)d_in[12];
    const float* pre_b2 = (const float*)d_in[13];
    const float* cw0_2  = (const float*)d_in[14];
    const float* cw1_2  = (const float*)d_in[15];
    const float* cb_2   = (const float*)d_in[16];
    const float* sw_2   = (const float*)d_in[17];
    const float* sb_2   = (const float*)d_in[18];
    const float* lw_2   = (const float*)d_in[19];
    const float* lb_2   = (const float*)d_in[20];
    const float* cls_w  = (const float*)d_in[21];
    const float* cls_b  = (const float*)d_in[22];
    float* out = (float*)d_out;

    void *p_xh, *p_tx1, *p_s, *p_t1, *p_xc;
    cudaGetSymbolAddress(&p_xh,  g_xh);
    cudaGetSymbolAddress(&p_tx1, g_tx1);
    cudaGetSymbolAddress(&p_s,   g_s);
    cudaGetSymbolAddress(&p_t1,  g_t1);
    cudaGetSymbolAddress(&p_xc,  g_xc);
    float* xh  = (float*)p_xh;
    float* tx1 = (float*)p_tx1;
    float* s   = (float*)p_s;
    float* t1  = (float*)p_t1;
    float* xc  = (float*)p_xc;

    prep_zero_kernel<<<(NN + 255)/256, 256>>>();
    prep_edge_kernel<<<(NE + 255)/256, 256>>>(ei, w);
    prep_node_kernel<<<(NN + 255)/256, 256>>>();
    scan_kernel<<<1, 1024>>>();
    fill_kernel<<<(NE + 255)/256, 256>>>(ei, w);

    run_cell(x,  pre_w1, pre_b1, cw0_1, cw1_1, cb_1, sw_1, sb_1, lw_1, lb_1,
             xh, tx1, s, t1, xc, FIN);
    run_cell(xc, pre_w2, pre_b2, cw0_2, cw1_2, cb_2, sw_2, sb_2, lw_2, lb_2,
             xh, tx1, s, t1, xc, HH);

    gemm_tc_kernel<F_BIAS><<<(NN + 127)/128, 256>>>(xc, cls_w, HH, nullptr, nullptr, 0,
                                                    cls_b, out, NN, CO);
    logsoftmax_kernel<<<(NN*32 + 255)/256, 256>>>(out);
}

// round 6
// speedup vs baseline: 3.5308x; 1.2372x over previous
#include <cuda_runtime.h>
#include <cuda_bf16.h>
#include <math.h>
#include <stdint.h>

#define NN   40000
#define NE   640000
#define FIN  512
#define HH   128
#define CO   40

// ---------------- scratch (device globals) ----------------
__device__ __align__(16) float g_xh [NN*HH];
__device__ __align__(16) float g_tx1[NN*HH];
__device__ __align__(16) float g_s  [NN*HH];
__device__ __align__(16) float g_xc [NN*HH];
__device__ float g_deg   [NN];
__device__ float g_dis   [NN];
__device__ float g_loopw [NN];
__device__ float g_invcnt[NN];
__device__ __align__(16) int g_cnt   [NN + 64];
__device__ int   g_cursor[NN];
__device__ int   g_rowptr[NN + 1];
__device__ int   g_bsum  [160];
__device__ __align__(16) int4 g_emeta[NE];   // {src, w(bits), coef(bits), 0} sorted by dst

// ---------------- graph prep ----------------
__global__ void prep_zero_kernel() {
    int n = blockIdx.x * blockDim.x + threadIdx.x;
    if (n < NN) { g_deg[n] = 0.0f; g_loopw[n] = 1.0f; g_cnt[n] = 0; g_cursor[n] = 0; }
}

__global__ void prep_edge_kernel(const int* __restrict__ ei, const float* __restrict__ w) {
    int e = blockIdx.x * blockDim.x + threadIdx.x;
    if (e >= NE) return;
    int s = ei[e], d = ei[NE + e];
    float we = w[e];
    if (s != d) {
        atomicAdd(&g_deg[s], we);
        atomicAdd(&g_cnt[d], 1);
    } else {
        g_loopw[s] = we;
    }
}

__global__ void prep_node_kernel() {
    int n = blockIdx.x * blockDim.x + threadIdx.x;
    if (n >= NN) return;
    float dg = g_deg[n];
    g_dis[n]    = (dg > 0.0f) ? rsqrtf(dg) : 0.0f;
    g_invcnt[n] = 1.0f / ((float)g_cnt[n] + 1.0f);
}

// ---------------- multi-block exclusive scan: g_cnt -> g_rowptr ----------------
// phase 1: 160 blocks x 256 -> block sums
__global__ __launch_bounds__(256)
void scan1_kernel() {
    __shared__ int swarp[8];
    int idx = blockIdx.x * 256 + threadIdx.x;
    int lane = threadIdx.x & 31, wid = threadIdx.x >> 5;
    int v = (idx < NN) ? g_cnt[idx] : 0;
    int sum = v;
    #pragma unroll
    for (int o = 16; o > 0; o >>= 1) sum += __shfl_xor_sync(0xffffffffu, sum, o);
    if (lane == 0) swarp[wid] = sum;
    __syncthreads();
    if (threadIdx.x == 0) {
        int t = 0;
        #pragma unroll
        for (int i = 0; i < 8; i++) t += swarp[i];
        g_bsum[blockIdx.x] = t;
    }
}

// phase 2: 1 block scans the 160 block sums (exclusive, in place)
__global__ __launch_bounds__(256)
void scan2_kernel() {
    __shared__ int swarp[8];
    int t = threadIdx.x;
    int lane = t & 31, wid = t >> 5;
    int v = (t < 160) ? g_bsum[t] : 0;
    int incl = v;
    #pragma unroll
    for (int o = 1; o < 32; o <<= 1) {
        int u = __shfl_up_sync(0xffffffffu, incl, o);
        if (lane >= o) incl += u;
    }
    if (lane == 31) swarp[wid] = incl;
    __syncthreads();
    if (wid == 0 && lane < 8) {
        int x = swarp[lane];
        int ix = x;
        #pragma unroll
        for (int o = 1; o < 8; o <<= 1) {
            int u = __shfl_up_sync(0xffu, ix, o);
            if (lane >= o) ix += u;
        }
        swarp[lane] = ix - x;
    }
    __syncthreads();
    if (t < 160) g_bsum[t] = swarp[wid] + incl - v;   // exclusive prefix
}

// phase 3: 160 blocks emit rowptr
__global__ __launch_bounds__(256)
void scan3_kernel() {
    __shared__ int swarp[8];
    int idx = blockIdx.x * 256 + threadIdx.x;
    int lane = threadIdx.x & 31, wid = threadIdx.x >> 5;
    int v = (idx < NN) ? g_cnt[idx] : 0;
    int incl = v;
    #pragma unroll
    for (int o = 1; o < 32; o <<= 1) {
        int u = __shfl_up_sync(0xffffffffu, incl, o);
        if (lane >= o) incl += u;
    }
    if (lane == 31) swarp[wid] = incl;
    __syncthreads();
    if (wid == 0 && lane < 8) {
        int x = swarp[lane];
        int ix = x;
        #pragma unroll
        for (int o = 1; o < 8; o <<= 1) {
            int u = __shfl_up_sync(0xffu, ix, o);
            if (lane >= o) ix += u;
        }
        swarp[lane] = ix - x;
    }
    __syncthreads();
    int excl = g_bsum[blockIdx.x] + swarp[wid] + incl - v;
    if (idx < NN)      g_rowptr[idx] = excl;
    if (idx == NN - 1) g_rowptr[NN]  = excl + v;
}

// ---------------- fill CSR with packed edge meta ----------------
__global__ void fill_kernel(const int* __restrict__ ei, const float* __restrict__ w) {
    int e = blockIdx.x * blockDim.x + threadIdx.x;
    if (e >= NE) return;
    int s = ei[e], d = ei[NE + e];
    if (s == d) return;
    float we   = w[e];
    float coef = -g_dis[s] * we * g_dis[d];
    int pos = g_rowptr[d] + atomicAdd(&g_cursor[d], 1);
    g_emeta[pos] = make_int4(s, __float_as_int(we), __float_as_int(coef), 0);
}

// ---------------- CSR gather-reduce: warp per node ----------------
__global__ __launch_bounds__(256)
void aggregate_kernel(const float4* __restrict__ xh,
                      float4* __restrict__ tx1, float4* __restrict__ s) {
    int n    = (blockIdx.x * blockDim.x + threadIdx.x) >> 5;
    int lane = threadIdx.x & 31;
    if (n >= NN) return;
    int beg = g_rowptr[n], end = g_rowptr[n + 1];

    float lw = g_loopw[n];
    float4 xv = xh[n * 32 + lane];
    float4 a = make_float4(0.f, 0.f, 0.f, 0.f);
    float4 b = make_float4(lw * xv.x, lw * xv.y, lw * xv.z, lw * xv.w);

    int e = beg;
    for (; e + 4 <= end; e += 4) {
        int4 m0 = g_emeta[e+0], m1 = g_emeta[e+1], m2 = g_emeta[e+2], m3 = g_emeta[e+3];
        float4 v0 = xh[m0.x * 32 + lane];
        float4 v1 = xh[m1.x * 32 + lane];
        float4 v2 = xh[m2.x * 32 + lane];
        float4 v3 = xh[m3.x * 32 + lane];
        float w0 = __int_as_float(m0.y), c0 = __int_as_float(m0.z);
        float w1 = __int_as_float(m1.y), c1 = __int_as_float(m1.z);
        float w2 = __int_as_float(m2.y), c2 = __int_as_float(m2.z);
        float w3 = __int_as_float(m3.y), c3 = __int_as_float(m3.z);
        a.x += c0*v0.x + c1*v1.x + c2*v2.x + c3*v3.x;
        a.y += c0*v0.y + c1*v1.y + c2*v2.y + c3*v3.y;
        a.z += c0*v0.z + c1*v1.z + c2*v2.z + c3*v3.z;
        a.w += c0*v0.w + c1*v1.w + c2*v2.w + c3*v3.w;
        b.x += w0*v0.x + w1*v1.x + w2*v2.x + w3*v3.x;
        b.y += w0*v0.y + w1*v1.y + w2*v2.y + w3*v3.y;
        b.z += w0*v0.z + w1*v1.z + w2*v2.z + w3*v3.z;
        b.w += w0*v0.w + w1*v1.w + w2*v2.w + w3*v3.w;
    }
    for (; e < end; e++) {
        int4 m = g_emeta[e];
        float we = __int_as_float(m.y);
        float cf = __int_as_float(m.z);
        float4 v = xh[m.x * 32 + lane];
        a.x += cf * v.x; a.y += cf * v.y; a.z += cf * v.z; a.w += cf * v.w;
        b.x += we * v.x; b.y += we * v.y; b.z += we * v.z; b.w += we * v.w;
    }
    float ic = g_invcnt[n];
    tx1[n * 32 + lane] = a;
    s  [n * 32 + lane] = make_float4(b.x * ic, b.y * ic, b.z * ic, b.w * ic);
}

// ---------------- common helpers ----------------
#define F_BIAS       1
#define F_LEAKY      2
#define F_ADDC_PRE   4
#define F_ADDC_POST  8

__device__ __forceinline__ float tf32r(float x) {
    uint32_t u;
    asm("cvt.rna.tf32.f32 %0, %1;" : "=r"(u) : "f"(x));
    return __uint_as_float(u);
}

// ---------------- generic TF32 GEMM (pre-GEMM + classifier) ----------------
template<int FLAGS>
__global__ __launch_bounds__(256)
void gemm_tc_kernel(const float* __restrict__ A, const float* __restrict__ B,
                    const float* __restrict__ bias, float* __restrict__ C,
                    int Nrows, int K, int M) {
    __shared__ float As[2][16][136];
    __shared__ float Bs[2][16][136];

    const int tid   = threadIdx.x;
    const int r0    = blockIdx.x * 128;
    const int wid   = tid >> 5;
    const int lane  = tid & 31;
    const int grp   = lane >> 2;
    const int qid   = lane & 3;
    const int warpM = wid & 1;
    const int warpN = wid >> 1;

    float acc[4][4][4];
    #pragma unroll
    for (int mi = 0; mi < 4; mi++)
        #pragma unroll
        for (int ni = 0; ni < 4; ni++)
            #pragma unroll
            for (int r = 0; r < 4; r++) acc[mi][ni][r] = 0.0f;

    const int nt = K >> 4;

    auto load_tile = [&](int k0, int buf) {
        #pragma unroll
        for (int i = 0; i < 2; i++) {
            int idx = tid + i * 256;
            int row = idx >> 2;
            int kc  = (idx & 3) << 2;
            int gr  = r0 + row;
            float4 v = make_float4(0.f, 0.f, 0.f, 0.f);
            if (gr < Nrows) v = *(const float4*)&A[(size_t)gr * K + k0 + kc];
            As[buf][kc+0][row] = tf32r(v.x);
            As[buf][kc+1][row] = tf32r(v.y);
            As[buf][kc+2][row] = tf32r(v.z);
            As[buf][kc+3][row] = tf32r(v.w);
        }
        #pragma unroll
        for (int i = 0; i < 2; i++) {
            int idx = tid + i * 256;
            int kr  = idx >> 5;
            int col = (idx & 31) << 2;
            float4 v = make_float4(0.f, 0.f, 0.f, 0.f);
            if (col < M) v = *(const float4*)&B[(size_t)(k0 + kr) * M + col];
            v.x = tf32r(v.x); v.y = tf32r(v.y); v.z = tf32r(v.z); v.w = tf32r(v.w);
            *(float4*)&Bs[buf][kr][col] = v;
        }
    };

    load_tile(0, 0);
    __syncthreads();

    int buf = 0;
    for (int t = 0; t < nt; t++) {
        if (t + 1 < nt) load_tile((t + 1) << 4, buf ^ 1);

        #pragma unroll
        for (int ks = 0; ks < 16; ks += 8) {
            uint32_t af[4][4];
            uint32_t bf[4][2];
            #pragma unroll
            for (int mi = 0; mi < 4; mi++) {
                int m = warpM * 64 + mi * 16 + grp;
                af[mi][0] = __float_as_uint(As[buf][ks + qid    ][m]);
                af[mi][1] = __float_as_uint(As[buf][ks + qid    ][m + 8]);
                af[mi][2] = __float_as_uint(As[buf][ks + qid + 4][m]);
                af[mi][3] = __float_as_uint(As[buf][ks + qid + 4][m + 8]);
            }
            #pragma unroll
            for (int ni = 0; ni < 4; ni++) {
                int n = warpN * 32 + ni * 8 + grp;
                bf[ni][0] = __float_as_uint(Bs[buf][ks + qid    ][n]);
                bf[ni][1] = __float_as_uint(Bs[buf][ks + qid + 4][n]);
            }
            #pragma unroll
            for (int mi = 0; mi < 4; mi++)
                #pragma unroll
                for (int ni = 0; ni < 4; ni++) {
                    asm volatile(
                        "mma.sync.aligned.m16n8k8.row.col.f32.tf32.tf32.f32 "
                        "{%0,%1,%2,%3}, {%4,%5,%6,%7}, {%8,%9}, {%0,%1,%2,%3};"
                        : "+f"(acc[mi][ni][0]), "+f"(acc[mi][ni][1]),
                          "+f"(acc[mi][ni][2]), "+f"(acc[mi][ni][3])
                        : "r"(af[mi][0]), "r"(af[mi][1]), "r"(af[mi][2]), "r"(af[mi][3]),
                          "r"(bf[ni][0]), "r"(bf[ni][1]));
                }
        }
        __syncthreads();
        buf ^= 1;
    }

    #pragma unroll
    for (int mi = 0; mi < 4; mi++) {
        #pragma unroll
        for (int half = 0; half < 2; half++) {
            int row = r0 + warpM * 64 + mi * 16 + grp + half * 8;
            if (row >= Nrows) continue;
            #pragma unroll
            for (int ni = 0; ni < 4; ni++) {
                int col = warpN * 32 + ni * 8 + qid * 2;
                if (col >= M) continue;
                size_t off = (size_t)row * M + col;
                float vx = acc[mi][ni][half * 2 + 0];
                float vy = acc[mi][ni][half * 2 + 1];
                if (FLAGS & F_BIAS)     { vx += bias[col]; vy += bias[col + 1]; }
                if (FLAGS & F_LEAKY) {
                    vx = (vx > 0.f) ? vx : 0.01f * vx;
                    vy = (vy > 0.f) ? vy : 0.01f * vy;
                }
                *(float2*)&C[off] = make_float2(vx, vy);
            }
        }
    }
}

// ---------------- cell megakernel ----------------
// Phase A: acc = xh@cw0 + tx1@cw1 ; T = leaky(acc + cb)          (T in smem)
// Phase B: acc = s@sw            ; T += leaky(acc + sb)
// Phase C: acc = T@lw            ; x_out = acc + lb
// smem: AS (2*16*136) | BS (2*16*136) | T (128*136)  = 104448 bytes
#define SMEM_MEGA ((2*16*136 + 2*16*136 + 128*136) * 4)

__global__ __launch_bounds__(256)
void cell_post_kernel(const float* __restrict__ xh, const float* __restrict__ tx1,
                      const float* __restrict__ s,
                      const float* __restrict__ cw0, const float* __restrict__ cw1,
                      const float* __restrict__ cb,
                      const float* __restrict__ sw, const float* __restrict__ sb,
                      const float* __restrict__ lw, const float* __restrict__ lb,
                      float* __restrict__ x_out, int Nrows) {
    extern __shared__ float sm[];
    float* AS = sm;                    // [buf*16+k][136]
    float* BS = sm + 2*16*136;
    float* T  = sm + 4*16*136;         // [k][136]

    const int tid   = threadIdx.x;
    const int r0    = blockIdx.x * 128;
    const int wid   = tid >> 5;
    const int lane  = tid & 31;
    const int grp   = lane >> 2;
    const int qid   = lane & 3;
    const int warpM = wid & 1;
    const int warpN = wid >> 1;

    float acc[4][4][4];

    auto zero_acc = [&]() {
        #pragma unroll
        for (int mi = 0; mi < 4; mi++)
            #pragma unroll
            for (int ni = 0; ni < 4; ni++)
                #pragma unroll
                for (int r = 0; r < 4; r++) acc[mi][ni][r] = 0.0f;
    };

    auto load_ab = [&](const float* __restrict__ A, const float* __restrict__ B,
                       int kk0, int buf) {
        #pragma unroll
        for (int i = 0; i < 2; i++) {
            int idx = tid + i * 256;
            int row = idx >> 2;
            int kc  = (idx & 3) << 2;
            int gr  = r0 + row;
            float4 v = make_float4(0.f, 0.f, 0.f, 0.f);
            if (gr < Nrows) v = *(const float4*)&A[(size_t)gr * HH + kk0 + kc];
            AS[(buf*16 + kc+0)*136 + row] = tf32r(v.x);
            AS[(buf*16 + kc+1)*136 + row] = tf32r(v.y);
            AS[(buf*16 + kc+2)*136 + row] = tf32r(v.z);
            AS[(buf*16 + kc+3)*136 + row] = tf32r(v.w);
        }
        #pragma unroll
        for (int i = 0; i < 2; i++) {
            int idx = tid + i * 256;
            int kr  = idx >> 5;
            int col = (idx & 31) << 2;
            float4 v = *(const float4*)&B[(size_t)(kk0 + kr) * HH + col];
            v.x = tf32r(v.x); v.y = tf32r(v.y); v.z = tf32r(v.z); v.w = tf32r(v.w);
            *(float4*)&BS[(buf*16 + kr)*136 + col] = v;
        }
    };

    auto load_b = [&](const float* __restrict__ B, int kk0, int buf) {
        #pragma unroll
        for (int i = 0; i < 2; i++) {
            int idx = tid + i * 256;
            int kr  = idx >> 5;
            int col = (idx & 31) << 2;
            float4 v = *(const float4*)&B[(size_t)(kk0 + kr) * HH + col];
            v.x = tf32r(v.x); v.y = tf32r(v.y); v.z = tf32r(v.z); v.w = tf32r(v.w);
            *(float4*)&BS[(buf*16 + kr)*136 + col] = v;
        }
    };

    auto compute16 = [&](const float* __restrict__ Ab, const float* __restrict__ Bb) {
        #pragma unroll
        for (int ks = 0; ks < 16; ks += 8) {
            uint32_t af[4][4];
            uint32_t bf[4][2];
            #pragma unroll
            for (int mi = 0; mi < 4; mi++) {
                int m = warpM * 64 + mi * 16 + grp;
                af[mi][0] = __float_as_uint(Ab[(ks + qid    )*136 + m]);
                af[mi][1] = __float_as_uint(Ab[(ks + qid    )*136 + m + 8]);
                af[mi][2] = __float_as_uint(Ab[(ks + qid + 4)*136 + m]);
                af[mi][3] = __float_as_uint(Ab[(ks + qid + 4)*136 + m + 8]);
            }
            #pragma unroll
            for (int ni = 0; ni < 4; ni++) {
                int n = warpN * 32 + ni * 8 + grp;
                bf[ni][0] = __float_as_uint(Bb[(ks + qid    )*136 + n]);
                bf[ni][1] = __float_as_uint(Bb[(ks + qid + 4)*136 + n]);
            }
            #pragma unroll
            for (int mi = 0; mi < 4; mi++)
                #pragma unroll
                for (int ni = 0; ni < 4; ni++) {
                    asm volatile(
                        "mma.sync.aligned.m16n8k8.row.col.f32.tf32.tf32.f32 "
                        "{%0,%1,%2,%3}, {%4,%5,%6,%7}, {%8,%9}, {%0,%1,%2,%3};"
                        : "+f"(acc[mi][ni][0]), "+f"(acc[mi][ni][1]),
                          "+f"(acc[mi][ni][2]), "+f"(acc[mi][ni][3])
                        : "r"(af[mi][0]), "r"(af[mi][1]), "r"(af[mi][2]), "r"(af[mi][3]),
                          "r"(bf[ni][0]), "r"(bf[ni][1]));
                }
        }
    };

    // ---- Phase A: acc = xh@cw0 + tx1@cw1 over 16 k-tiles ----
    zero_acc();
    load_ab(xh, cw0, 0, 0);
    __syncthreads();
    int buf = 0;
    #pragma unroll 1
    for (int t = 0; t < 16; t++) {
        if (t + 1 < 16) {
            int tn = t + 1;
            const float* An = (tn < 8) ? xh  : tx1;
            const float* Bn = (tn < 8) ? cw0 : cw1;
            load_ab(An, Bn, (tn & 7) << 4, buf ^ 1);
        }
        compute16(AS + buf*16*136, BS + buf*16*136);
        __syncthreads();
        buf ^= 1;
    }
    // epilogue -> T = leaky(acc + cb)
    #pragma unroll
    for (int mi = 0; mi < 4; mi++)
        #pragma unroll
        for (int half = 0; half < 2; half++) {
            int rl = warpM * 64 + mi * 16 + grp + half * 8;
            #pragma unroll
            for (int ni = 0; ni < 4; ni++) {
                int col = warpN * 32 + ni * 8 + qid * 2;
                float vx = acc[mi][ni][half*2+0] + cb[col];
                float vy = acc[mi][ni][half*2+1] + cb[col+1];
                vx = (vx > 0.f) ? vx : 0.01f * vx;
                vy = (vy > 0.f) ? vy : 0.01f * vy;
                T[(col  )*136 + rl] = vx;
                T[(col+1)*136 + rl] = vy;
            }
        }

    // ---- Phase B: acc = s@sw over 8 k-tiles ----
    zero_acc();
    load_ab(s, sw, 0, 0);
    __syncthreads();
    buf = 0;
    #pragma unroll 1
    for (int t = 0; t < 8; t++) {
        if (t + 1 < 8) load_ab(s, sw, (t + 1) << 4, buf ^ 1);
        compute16(AS + buf*16*136, BS + buf*16*136);
        __syncthreads();
        buf ^= 1;
    }
    // epilogue -> T += leaky(acc + sb)  (same owner as phase A; then tf32 round)
    #pragma unroll
    for (int mi = 0; mi < 4; mi++)
        #pragma unroll
        for (int half = 0; half < 2; half++) {
            int rl = warpM * 64 + mi * 16 + grp + half * 8;
            #pragma unroll
            for (int ni = 0; ni < 4; ni++) {
                int col = warpN * 32 + ni * 8 + qid * 2;
                float vx = acc[mi][ni][half*2+0] + sb[col];
                float vy = acc[mi][ni][half*2+1] + sb[col+1];
                vx = (vx > 0.f) ? vx : 0.01f * vx;
                vy = (vy > 0.f) ? vy : 0.01f * vy;
                T[(col  )*136 + rl] = tf32r(T[(col  )*136 + rl] + vx);
                T[(col+1)*136 + rl] = tf32r(T[(col+1)*136 + rl] + vy);
            }
        }

    // ---- Phase C: acc = T@lw over 8 k-tiles (A straight from smem T) ----
    zero_acc();
    load_b(lw, 0, 0);
    __syncthreads();                      // T fully written, BS tile 0 ready
    buf = 0;
    #pragma unroll 1
    for (int t = 0; t < 8; t++) {
        if (t + 1 < 8) load_b(lw, (t + 1) << 4, buf ^ 1);
        compute16(T + t*16*136, BS + buf*16*136);
        __syncthreads();
        buf ^= 1;
    }
    // final epilogue -> x_out = acc + lb
    #pragma unroll
    for (int mi = 0; mi < 4; mi++)
        #pragma unroll
        for (int half = 0; half < 2; half++) {
            int row = r0 + warpM * 64 + mi * 16 + grp + half * 8;
            if (row >= Nrows) continue;
            #pragma unroll
            for (int ni = 0; ni < 4; ni++) {
                int col = warpN * 32 + ni * 8 + qid * 2;
                float vx = acc[mi][ni][half*2+0] + lb[col];
                float vy = acc[mi][ni][half*2+1] + lb[col+1];
                *(float2*)&x_out[(size_t)row * HH + col] = make_float2(vx, vy);
            }
        }
}

// ---------------- log_softmax ----------------
__global__ __launch_bounds__(256)
void logsoftmax_kernel(float* __restrict__ out) {
    int row  = (blockIdx.x * blockDim.x + threadIdx.x) >> 5;
    int lane = threadIdx.x & 31;
    if (row >= NN) return;
    float* p = out + (size_t)row * CO;
    float v0 = p[lane];
    float v1 = (lane < CO - 32) ? p[32 + lane] : -3.4e38f;
    float m = fmaxf(v0, v1);
    #pragma unroll
    for (int o = 16; o > 0; o >>= 1) m = fmaxf(m, __shfl_xor_sync(0xffffffffu, m, o));
    float e = expf(v0 - m) + ((lane < CO - 32) ? expf(v1 - m) : 0.0f);
    #pragma unroll
    for (int o = 16; o > 0; o >>= 1) e += __shfl_xor_sync(0xffffffffu, e, o);
    float ls = m + logf(e);
    p[lane] = v0 - ls;
    if (lane < CO - 32) p[32 + lane] = v1 - ls;
}

// ---------------- launch ----------------
extern "C" void kernel_launch(void* const* d_in, const int* in_sizes, int n_in,
                              void* d_out, int out_size) {
    const float* x    = (const float*)d_in[0];
    const int*   ei   = (const int*)  d_in[1];
    const float* w    = (const float*)d_in[2];
    const float* pre_w1 = (const float*)d_in[3];
    const float* pre_b1 = (const float*)d_in[4];
    const float* cw0_1  = (const float*)d_in[5];
    const float* cw1_1  = (const float*)d_in[6];
    const float* cb_1   = (const float*)d_in[7];
    const float* sw_1   = (const float*)d_in[8];
    const float* sb_1   = (const float*)d_in[9];
    const float* lw_1   = (const float*)d_in[10];
    const float* lb_1   = (const float*)d_in[11];
    const float* pre_w2 = (const float*)d_in[12];
    const float* pre_b2 = (const float*)d_in[13];
    const float* cw0_2  = (const float*)d_in[14];
    const float* cw1_2  = (const float*)d_in[15];
    const float* cb_2   = (const float*)d_in[16];
    const float* sw_2   = (const float*)d_in[17];
    const float* sb_2   = (const float*)d_in[18];
    const float* lw_2   = (const float*)d_in[19];
    const float* lb_2   = (const float*)d_in[20];
    const float* cls_w  = (const float*)d_in[21];
    const float* cls_b  = (const float*)d_in[22];
    float* out = (float*)d_out;

    void *p_xh, *p_tx1, *p_s, *p_xc;
    cudaGetSymbolAddress(&p_xh,  g_xh);
    cudaGetSymbolAddress(&p_tx1, g_tx1);
    cudaGetSymbolAddress(&p_s,   g_s);
    cudaGetSymbolAddress(&p_xc,  g_xc);
    float* xh  = (float*)p_xh;
    float* tx1 = (float*)p_tx1;
    float* s   = (float*)p_s;
    float* xc  = (float*)p_xc;

    static bool attr_done = false;
    if (!attr_done) {
        cudaFuncSetAttribute(cell_post_kernel,
                             cudaFuncAttributeMaxDynamicSharedMemorySize, SMEM_MEGA);
        attr_done = true;
    }

    const int GB = (NN + 127) / 128;

    // graph prep + CSR build
    prep_zero_kernel<<<(NN + 255)/256, 256>>>();
    prep_edge_kernel<<<(NE + 255)/256, 256>>>(ei, w);
    prep_node_kernel<<<(NN + 255)/256, 256>>>();
    scan1_kernel<<<160, 256>>>();
    scan2_kernel<<<1, 256>>>();
    scan3_kernel<<<160, 256>>>();
    fill_kernel<<<(NE + 255)/256, 256>>>(ei, w);

    // ---- cell 1 ----
    gemm_tc_kernel<F_BIAS><<<GB, 256>>>(x, pre_w1, pre_b1, xh, NN, FIN, HH);
    aggregate_kernel<<<(NN * 32 + 255) / 256, 256>>>((const float4*)xh, (float4*)tx1, (float4*)s);
    cell_post_kernel<<<GB, 256, SMEM_MEGA>>>(xh, tx1, s, cw0_1, cw1_1, cb_1,
                                             sw_1, sb_1, lw_1, lb_1, xc, NN);
    // ---- cell 2 ----
    gemm_tc_kernel<F_BIAS><<<GB, 256>>>(xc, pre_w2, pre_b2, xh, NN, HH, HH);
    aggregate_kernel<<<(NN * 32 + 255) / 256, 256>>>((const float4*)xh, (float4*)tx1, (float4*)s);
    cell_post_kernel<<<GB, 256, SMEM_MEGA>>>(xh, tx1, s, cw0_2, cw1_2, cb_2,
                                             sw_2, sb_2, lw_2, lb_2, xc, NN);

    // classifier + log_softmax
    gemm_tc_kernel<F_BIAS><<<GB, 256>>>(xc, cls_w, cls_b, out, NN, HH, CO);
    logsoftmax_kernel<<<(NN*32 + 255)/256, 256>>>(out);
}

// round 8
// speedup vs baseline: 4.1008x; 1.1614x over previous
#include <cuda_runtime.h>
#include <cuda_bf16.h>
#include <math.h>
#include <stdint.h>

#define NN   40000
#define NE   640000
#define FIN  512
#define HH   128
#define CO   40

// ---------------- scratch (device globals) ----------------
__device__ __align__(16) float g_xh [NN*HH];
__device__ __align__(16) float g_tx1[NN*HH];
__device__ __align__(16) float g_s  [NN*HH];
__device__ __align__(16) float g_xc [NN*HH];
__device__ float g_deg   [NN];
__device__ float g_dis   [NN];
__device__ float g_loopw [NN];
__device__ float g_invcnt[NN];
__device__ __align__(16) int g_cnt   [NN + 64];
__device__ int   g_cursor[NN];
__device__ int   g_rowptr[NN + 1];
__device__ int   g_bsum  [160];
__device__ __align__(16) int4 g_emeta[NE];   // {src, w(bits), coef(bits), 0} sorted by dst

// ---------------- graph prep ----------------
__global__ void prep_zero_kernel() {
    int n = blockIdx.x * blockDim.x + threadIdx.x;
    if (n < NN) { g_deg[n] = 0.0f; g_loopw[n] = 1.0f; g_cnt[n] = 0; g_cursor[n] = 0; }
}

__global__ void prep_edge_kernel(const int* __restrict__ ei, const float* __restrict__ w) {
    int e = blockIdx.x * blockDim.x + threadIdx.x;
    if (e >= NE) return;
    int s = ei[e], d = ei[NE + e];
    float we = w[e];
    if (s != d) {
        atomicAdd(&g_deg[s], we);
        atomicAdd(&g_cnt[d], 1);
    } else {
        g_loopw[s] = we;
    }
}

__global__ void prep_node_kernel() {
    int n = blockIdx.x * blockDim.x + threadIdx.x;
    if (n >= NN) return;
    float dg = g_deg[n];
    g_dis[n]    = (dg > 0.0f) ? rsqrtf(dg) : 0.0f;
    g_invcnt[n] = 1.0f / ((float)g_cnt[n] + 1.0f);
}

// ---------------- multi-block exclusive scan ----------------
__global__ __launch_bounds__(256)
void scan1_kernel() {
    __shared__ int swarp[8];
    int idx = blockIdx.x * 256 + threadIdx.x;
    int lane = threadIdx.x & 31, wid = threadIdx.x >> 5;
    int v = (idx < NN) ? g_cnt[idx] : 0;
    int sum = v;
    #pragma unroll
    for (int o = 16; o > 0; o >>= 1) sum += __shfl_xor_sync(0xffffffffu, sum, o);
    if (lane == 0) swarp[wid] = sum;
    __syncthreads();
    if (threadIdx.x == 0) {
        int t = 0;
        #pragma unroll
        for (int i = 0; i < 8; i++) t += swarp[i];
        g_bsum[blockIdx.x] = t;
    }
}

__global__ __launch_bounds__(256)
void scan2_kernel() {
    __shared__ int swarp[8];
    int t = threadIdx.x;
    int lane = t & 31, wid = t >> 5;
    int v = (t < 160) ? g_bsum[t] : 0;
    int incl = v;
    #pragma unroll
    for (int o = 1; o < 32; o <<= 1) {
        int u = __shfl_up_sync(0xffffffffu, incl, o);
        if (lane >= o) incl += u;
    }
    if (lane == 31) swarp[wid] = incl;
    __syncthreads();
    if (wid == 0 && lane < 8) {
        int x = swarp[lane];
        int ix = x;
        #pragma unroll
        for (int o = 1; o < 8; o <<= 1) {
            int u = __shfl_up_sync(0xffu, ix, o);
            if (lane >= o) ix += u;
        }
        swarp[lane] = ix - x;
    }
    __syncthreads();
    if (t < 160) g_bsum[t] = swarp[wid] + incl - v;
}

__global__ __launch_bounds__(256)
void scan3_kernel() {
    __shared__ int swarp[8];
    int idx = blockIdx.x * 256 + threadIdx.x;
    int lane = threadIdx.x & 31, wid = threadIdx.x >> 5;
    int v = (idx < NN) ? g_cnt[idx] : 0;
    int incl = v;
    #pragma unroll
    for (int o = 1; o < 32; o <<= 1) {
        int u = __shfl_up_sync(0xffffffffu, incl, o);
        if (lane >= o) incl += u;
    }
    if (lane == 31) swarp[wid] = incl;
    __syncthreads();
    if (wid == 0 && lane < 8) {
        int x = swarp[lane];
        int ix = x;
        #pragma unroll
        for (int o = 1; o < 8; o <<= 1) {
            int u = __shfl_up_sync(0xffu, ix, o);
            if (lane >= o) ix += u;
        }
        swarp[lane] = ix - x;
    }
    __syncthreads();
    int excl = g_bsum[blockIdx.x] + swarp[wid] + incl - v;
    if (idx < NN)      g_rowptr[idx] = excl;
    if (idx == NN - 1) g_rowptr[NN]  = excl + v;
}

// ---------------- fill CSR ----------------
__global__ void fill_kernel(const int* __restrict__ ei, const float* __restrict__ w) {
    int e = blockIdx.x * blockDim.x + threadIdx.x;
    if (e >= NE) return;
    int s = ei[e], d = ei[NE + e];
    if (s == d) return;
    float we   = w[e];
    float coef = -g_dis[s] * we * g_dis[d];
    int pos = g_rowptr[d] + atomicAdd(&g_cursor[d], 1);
    g_emeta[pos] = make_int4(s, __float_as_int(we), __float_as_int(coef), 0);
}

// ---------------- CSR gather-reduce: warp per node ----------------
__global__ __launch_bounds__(256)
void aggregate_kernel(const float4* __restrict__ xh,
                      float4* __restrict__ tx1, float4* __restrict__ s) {
    int n    = (blockIdx.x * blockDim.x + threadIdx.x) >> 5;
    int lane = threadIdx.x & 31;
    if (n >= NN) return;
    int beg = g_rowptr[n], end = g_rowptr[n + 1];

    float lw = g_loopw[n];
    float4 xv = xh[n * 32 + lane];
    float4 a = make_float4(0.f, 0.f, 0.f, 0.f);
    float4 b = make_float4(lw * xv.x, lw * xv.y, lw * xv.z, lw * xv.w);

    int e = beg;
    for (; e + 4 <= end; e += 4) {
        int4 m0 = g_emeta[e+0], m1 = g_emeta[e+1], m2 = g_emeta[e+2], m3 = g_emeta[e+3];
        float4 v0 = xh[m0.x * 32 + lane];
        float4 v1 = xh[m1.x * 32 + lane];
        float4 v2 = xh[m2.x * 32 + lane];
        float4 v3 = xh[m3.x * 32 + lane];
        float w0 = __int_as_float(m0.y), c0 = __int_as_float(m0.z);
        float w1 = __int_as_float(m1.y), c1 = __int_as_float(m1.z);
        float w2 = __int_as_float(m2.y), c2 = __int_as_float(m2.z);
        float w3 = __int_as_float(m3.y), c3 = __int_as_float(m3.z);
        a.x += c0*v0.x + c1*v1.x + c2*v2.x + c3*v3.x;
        a.y += c0*v0.y + c1*v1.y + c2*v2.y + c3*v3.y;
        a.z += c0*v0.z + c1*v1.z + c2*v2.z + c3*v3.z;
        a.w += c0*v0.w + c1*v1.w + c2*v2.w + c3*v3.w;
        b.x += w0*v0.x + w1*v1.x + w2*v2.x + w3*v3.x;
        b.y += w0*v0.y + w1*v1.y + w2*v2.y + w3*v3.y;
        b.z += w0*v0.z + w1*v1.z + w2*v2.z + w3*v3.z;
        b.w += w0*v0.w + w1*v1.w + w2*v2.w + w3*v3.w;
    }
    for (; e < end; e++) {
        int4 m = g_emeta[e];
        float we = __int_as_float(m.y);
        float cf = __int_as_float(m.z);
        float4 v = xh[m.x * 32 + lane];
        a.x += cf * v.x; a.y += cf * v.y; a.z += cf * v.z; a.w += cf * v.w;
        b.x += we * v.x; b.y += we * v.y; b.z += we * v.z; b.w += we * v.w;
    }
    float ic = g_invcnt[n];
    tx1[n * 32 + lane] = a;
    s  [n * 32 + lane] = make_float4(b.x * ic, b.y * ic, b.z * ic, b.w * ic);
}

// ---------------- common GEMM helpers ----------------
#define F_BIAS 1

__device__ __forceinline__ void cp16(uint32_t dst, const void* src, bool valid) {
    int sz = valid ? 16 : 0;
    asm volatile("cp.async.cg.shared.global [%0], [%1], 16, %2;"
                 :: "r"(dst), "l"(src), "r"(sz));
}
#define CP_COMMIT() asm volatile("cp.async.commit_group;")
#define CP_WAIT(N)  asm volatile("cp.async.wait_group %0;" :: "n"(N))

// round-to-nearest tf32 at fragment load (unbiased -> keeps rel_err ~1.2e-4)
__device__ __forceinline__ uint32_t ldtf(float x) {
    uint32_t u;
    asm("cvt.rna.tf32.f32 %0, %1;" : "=r"(u) : "f"(x));
    return u;
}

#define MMA_TF32(acc, af, bf)                                                   \
    asm volatile(                                                               \
        "mma.sync.aligned.m16n8k8.row.col.f32.tf32.tf32.f32 "                   \
        "{%0,%1,%2,%3}, {%4,%5,%6,%7}, {%8,%9}, {%0,%1,%2,%3};"                 \
        : "+f"((acc)[0]), "+f"((acc)[1]), "+f"((acc)[2]), "+f"((acc)[3])        \
        : "r"((af)[0]), "r"((af)[1]), "r"((af)[2]), "r"((af)[3]),               \
          "r"((bf)[0]), "r"((bf)[1]))

// A tile: [128 rows][16 k] stride 20 floats; B tile: [16 k][<=128 n] stride 136
#define A_TILE_F (128 * 20)     // 2560 floats
#define B_TILE_F (16 * 136)     // 2176 floats

// ---------------- standalone TF32 GEMM, 4-stage cp.async pipeline ----------------
#define SMEM_GEMM ((4 * A_TILE_F + 4 * B_TILE_F) * 4)

template<int FLAGS>
__global__ __launch_bounds__(256)
void gemm_tc_kernel(const float* __restrict__ A, const float* __restrict__ B,
                    const float* __restrict__ bias, float* __restrict__ C,
                    int Nrows, int K, int M) {
    extern __shared__ float sm[];
    float* AS = sm;
    float* BS = sm + 4 * A_TILE_F;

    const int tid   = threadIdx.x;
    const int r0    = blockIdx.x * 128;
    const int wid   = tid >> 5;
    const int lane  = tid & 31;
    const int grp   = lane >> 2;
    const int qid   = lane & 3;
    const int warpM = wid & 1;
    const int warpN = wid >> 1;

    float acc[4][4][4];
    #pragma unroll
    for (int mi = 0; mi < 4; mi++)
        #pragma unroll
        for (int ni = 0; ni < 4; ni++)
            #pragma unroll
            for (int r = 0; r < 4; r++) acc[mi][ni][r] = 0.0f;

    const int nt = K >> 4;

    auto issue = [&](int t, int stg) {
        int k0 = t << 4;
        float* as = AS + stg * A_TILE_F;
        float* bs = BS + stg * B_TILE_F;
        #pragma unroll
        for (int i = 0; i < 2; i++) {
            int idx = tid + i * 256;
            int row = idx >> 2, kc = (idx & 3) << 2;
            int gr  = r0 + row;
            cp16((uint32_t)__cvta_generic_to_shared(as + row * 20 + kc),
                 A + (size_t)gr * K + k0 + kc, gr < Nrows);
        }
        #pragma unroll
        for (int i = 0; i < 2; i++) {
            int idx = tid + i * 256;
            int kr = idx >> 5, col = (idx & 31) << 2;
            cp16((uint32_t)__cvta_generic_to_shared(bs + kr * 136 + col),
                 B + (size_t)(k0 + kr) * M + col, col < M);
        }
        CP_COMMIT();
    };

    int npre = (nt < 3) ? nt : 3;
    for (int t = 0; t < npre; t++) issue(t, t);

    for (int t = 0; t < nt; t++) {
        CP_WAIT(2);
        __syncthreads();
        int tn = t + 3;
        if (tn < nt) issue(tn, tn & 3);

        const float* as = AS + (t & 3) * A_TILE_F;
        const float* bs = BS + (t & 3) * B_TILE_F;
        #pragma unroll
        for (int ks = 0; ks < 16; ks += 8) {
            uint32_t af[4][4], bf[4][2];
            #pragma unroll
            for (int mi = 0; mi < 4; mi++) {
                int m = warpM * 64 + mi * 16 + grp;
                af[mi][0] = ldtf(as[(m    ) * 20 + ks + qid]);
                af[mi][1] = ldtf(as[(m + 8) * 20 + ks + qid]);
                af[mi][2] = ldtf(as[(m    ) * 20 + ks + qid + 4]);
                af[mi][3] = ldtf(as[(m + 8) * 20 + ks + qid + 4]);
            }
            #pragma unroll
            for (int ni = 0; ni < 4; ni++) {
                int n = warpN * 32 + ni * 8 + grp;
                bf[ni][0] = ldtf(bs[(ks + qid    ) * 136 + n]);
                bf[ni][1] = ldtf(bs[(ks + qid + 4) * 136 + n]);
            }
            #pragma unroll
            for (int mi = 0; mi < 4; mi++)
                #pragma unroll
                for (int ni = 0; ni < 4; ni++)
                    MMA_TF32(acc[mi][ni], af[mi], bf[ni]);
        }
    }

    #pragma unroll
    for (int mi = 0; mi < 4; mi++) {
        #pragma unroll
        for (int half = 0; half < 2; half++) {
            int row = r0 + warpM * 64 + mi * 16 + grp + half * 8;
            if (row >= Nrows) continue;
            #pragma unroll
            for (int ni = 0; ni < 4; ni++) {
                int col = warpN * 32 + ni * 8 + qid * 2;
                if (col >= M) continue;
                size_t off = (size_t)row * M + col;
                float vx = acc[mi][ni][half * 2 + 0];
                float vy = acc[mi][ni][half * 2 + 1];
                if (FLAGS & F_BIAS) { vx += bias[col]; vy += bias[col + 1]; }
                *(float2*)&C[off] = make_float2(vx, vy);
            }
        }
    }
}

// ---------------- cell megakernel, 2-stage cp.async ----------------
// Phase A: acc = xh@cw0 + tx1@cw1 ; T = leaky(acc + cb)   (T in smem, [k][m] s136)
// Phase B: acc = s@sw             ; T += leaky(acc + sb)
// Phase C: acc = T@lw             ; x_out = acc + lb
#define SMEM_MEGA ((2 * A_TILE_F + 2 * B_TILE_F + 128 * 136) * 4)

__global__ __launch_bounds__(256)
void cell_post_kernel(const float* __restrict__ xh, const float* __restrict__ tx1,
                      const float* __restrict__ s,
                      const float* __restrict__ cw0, const float* __restrict__ cw1,
                      const float* __restrict__ cb,
                      const float* __restrict__ sw, const float* __restrict__ sb,
                      const float* __restrict__ lw, const float* __restrict__ lb,
                      float* __restrict__ x_out, int Nrows) {
    extern __shared__ float sm[];
    float* AS = sm;
    float* BS = sm + 2 * A_TILE_F;
    float* T  = sm + 2 * A_TILE_F + 2 * B_TILE_F;

    const int tid   = threadIdx.x;
    const int r0    = blockIdx.x * 128;
    const int wid   = tid >> 5;
    const int lane  = tid & 31;
    const int grp   = lane >> 2;
    const int qid   = lane & 3;
    const int warpM = wid & 1;
    const int warpN = wid >> 1;

    float acc[4][4][4];

    auto zero_acc = [&]() {
        #pragma unroll
        for (int mi = 0; mi < 4; mi++)
            #pragma unroll
            for (int ni = 0; ni < 4; ni++)
                #pragma unroll
                for (int r = 0; r < 4; r++) acc[mi][ni][r] = 0.0f;
    };

    auto issue_ab = [&](const float* __restrict__ A, const float* __restrict__ B,
                        int k0, int stg) {
        float* as = AS + stg * A_TILE_F;
        float* bs = BS + stg * B_TILE_F;
        #pragma unroll
        for (int i = 0; i < 2; i++) {
            int idx = tid + i * 256;
            int row = idx >> 2, kc = (idx & 3) << 2;
            int gr  = r0 + row;
            cp16((uint32_t)__cvta_generic_to_shared(as + row * 20 + kc),
                 A + (size_t)gr * HH + k0 + kc, gr < Nrows);
        }
        #pragma unroll
        for (int i = 0; i < 2; i++) {
            int idx = tid + i * 256;
            int kr = idx >> 5, col = (idx & 31) << 2;
            cp16((uint32_t)__cvta_generic_to_shared(bs + kr * 136 + col),
                 B + (size_t)(k0 + kr) * HH + col, true);
        }
        CP_COMMIT();
    };

    auto issue_b = [&](const float* __restrict__ B, int k0, int stg) {
        float* bs = BS + stg * B_TILE_F;
        #pragma unroll
        for (int i = 0; i < 2; i++) {
            int idx = tid + i * 256;
            int kr = idx >> 5, col = (idx & 31) << 2;
            cp16((uint32_t)__cvta_generic_to_shared(bs + kr * 136 + col),
                 B + (size_t)(k0 + kr) * HH + col, true);
        }
        CP_COMMIT();
    };

    auto compute_s = [&](const float* __restrict__ as, const float* __restrict__ bs) {
        #pragma unroll
        for (int ks = 0; ks < 16; ks += 8) {
            uint32_t af[4][4], bf[4][2];
            #pragma unroll
            for (int mi = 0; mi < 4; mi++) {
                int m = warpM * 64 + mi * 16 + grp;
                af[mi][0] = ldtf(as[(m    ) * 20 + ks + qid]);
                af[mi][1] = ldtf(as[(m + 8) * 20 + ks + qid]);
                af[mi][2] = ldtf(as[(m    ) * 20 + ks + qid + 4]);
                af[mi][3] = ldtf(as[(m + 8) * 20 + ks + qid + 4]);
            }
            #pragma unroll
            for (int ni = 0; ni < 4; ni++) {
                int n = warpN * 32 + ni * 8 + grp;
                bf[ni][0] = ldtf(bs[(ks + qid    ) * 136 + n]);
                bf[ni][1] = ldtf(bs[(ks + qid + 4) * 136 + n]);
            }
            #pragma unroll
            for (int mi = 0; mi < 4; mi++)
                #pragma unroll
                for (int ni = 0; ni < 4; ni++)
                    MMA_TF32(acc[mi][ni], af[mi], bf[ni]);
        }
    };

    // transposed-A compute for phase C (A = T, [k][m] stride 136)
    auto compute_t = [&](const float* __restrict__ at, const float* __restrict__ bs) {
        #pragma unroll
        for (int ks = 0; ks < 16; ks += 8) {
            uint32_t af[4][4], bf[4][2];
            #pragma unroll
            for (int mi = 0; mi < 4; mi++) {
                int m = warpM * 64 + mi * 16 + grp;
                af[mi][0] = ldtf(at[(ks + qid    ) * 136 + m]);
                af[mi][1] = ldtf(at[(ks + qid    ) * 136 + m + 8]);
                af[mi][2] = ldtf(at[(ks + qid + 4) * 136 + m]);
                af[mi][3] = ldtf(at[(ks + qid + 4) * 136 + m + 8]);
            }
            #pragma unroll
            for (int ni = 0; ni < 4; ni++) {
                int n = warpN * 32 + ni * 8 + grp;
                bf[ni][0] = ldtf(bs[(ks + qid    ) * 136 + n]);
                bf[ni][1] = ldtf(bs[(ks + qid + 4) * 136 + n]);
            }
            #pragma unroll
            for (int mi = 0; mi < 4; mi++)
                #pragma unroll
                for (int ni = 0; ni < 4; ni++)
                    MMA_TF32(acc[mi][ni], af[mi], bf[ni]);
        }
    };

    // ---- Phase A: 16 virtual tiles (xh/cw0 then tx1/cw1) ----
    zero_acc();
    issue_ab(xh, cw0, 0, 0);
    #pragma unroll 1
    for (int t = 0; t < 16; t++) {
        CP_WAIT(0);
        __syncthreads();
        int tn = t + 1;
        if (tn < 16) {
            const float* An = (tn < 8) ? xh  : tx1;
            const float* Bn = (tn < 8) ? cw0 : cw1;
            issue_ab(An, Bn, (tn & 7) << 4, tn & 1);
        }
        compute_s(AS + (t & 1) * A_TILE_F, BS + (t & 1) * B_TILE_F);
    }
    #pragma unroll
    for (int mi = 0; mi < 4; mi++)
        #pragma unroll
        for (int half = 0; half < 2; half++) {
            int rl = warpM * 64 + mi * 16 + grp + half * 8;
            #pragma unroll
            for (int ni = 0; ni < 4; ni++) {
                int col = warpN * 32 + ni * 8 + qid * 2;
                float vx = acc[mi][ni][half*2+0] + cb[col];
                float vy = acc[mi][ni][half*2+1] + cb[col+1];
                vx = (vx > 0.f) ? vx : 0.01f * vx;
                vy = (vy > 0.f) ? vy : 0.01f * vy;
                T[(col  ) * 136 + rl] = vx;
                T[(col+1) * 136 + rl] = vy;
            }
        }

    // ---- Phase B: 8 tiles of s@sw ----
    zero_acc();
    issue_ab(s, sw, 0, 0);
    #pragma unroll 1
    for (int t = 0; t < 8; t++) {
        CP_WAIT(0);
        __syncthreads();
        if (t + 1 < 8) issue_ab(s, sw, (t + 1) << 4, (t + 1) & 1);
        compute_s(AS + (t & 1) * A_TILE_F, BS + (t & 1) * B_TILE_F);
    }
    #pragma unroll
    for (int mi = 0; mi < 4; mi++)
        #pragma unroll
        for (int half = 0; half < 2; half++) {
            int rl = warpM * 64 + mi * 16 + grp + half * 8;
            #pragma unroll
            for (int ni = 0; ni < 4; ni++) {
                int col = warpN * 32 + ni * 8 + qid * 2;
                float vx = acc[mi][ni][half*2+0] + sb[col];
                float vy = acc[mi][ni][half*2+1] + sb[col+1];
                vx = (vx > 0.f) ? vx : 0.01f * vx;
                vy = (vy > 0.f) ? vy : 0.01f * vy;
                T[(col  ) * 136 + rl] += vx;
                T[(col+1) * 136 + rl] += vy;
            }
        }
    __syncthreads();   // all T writes visible before phase C reads

    // ---- Phase C: 8 tiles of T@lw (A from smem T) ----
    zero_acc();
    issue_b(lw, 0, 0);
    #pragma unroll 1
    for (int t = 0; t < 8; t++) {
        CP_WAIT(0);
        __syncthreads();
        if (t + 1 < 8) issue_b(lw, (t + 1) << 4, (t + 1) & 1);
        compute_t(T + t * 16 * 136, BS + (t & 1) * B_TILE_F);
    }
    #pragma unroll
    for (int mi = 0; mi < 4; mi++)
        #pragma unroll
        for (int half = 0; half < 2; half++) {
            int row = r0 + warpM * 64 + mi * 16 + grp + half * 8;
            if (row >= Nrows) continue;
            #pragma unroll
            for (int ni = 0; ni < 4; ni++) {
                int col = warpN * 32 + ni * 8 + qid * 2;
                float vx = acc[mi][ni][half*2+0] + lb[col];
                float vy = acc[mi][ni][half*2+1] + lb[col+1];
                *(float2*)&x_out[(size_t)row * HH + col] = make_float2(vx, vy);
            }
        }
}

// ---------------- log_softmax ----------------
__global__ __launch_bounds__(256)
void logsoftmax_kernel(float* __restrict__ out) {
    int row  = (blockIdx.x * blockDim.x + threadIdx.x) >> 5;
    int lane = threadIdx.x & 31;
    if (row >= NN) return;
    float* p = out + (size_t)row * CO;
    float v0 = p[lane];
    float v1 = (lane < CO - 32) ? p[32 + lane] : -3.4e38f;
    float m = fmaxf(v0, v1);
    #pragma unroll
    for (int o = 16; o > 0; o >>= 1) m = fmaxf(m, __shfl_xor_sync(0xffffffffu, m, o));
    float e = expf(v0 - m) + ((lane < CO - 32) ? expf(v1 - m) : 0.0f);
    #pragma unroll
    for (int o = 16; o > 0; o >>= 1) e += __shfl_xor_sync(0xffffffffu, e, o);
    float ls = m + logf(e);
    p[lane] = v0 - ls;
    if (lane < CO - 32) p[32 + lane] = v1 - ls;
}

// ---------------- launch ----------------
extern "C" void kernel_launch(void* const* d_in, const int* in_sizes, int n_in,
                              void* d_out, int out_size) {
    const float* x    = (const float*)d_in[0];
    const int*   ei   = (const int*)  d_in[1];
    const float* w    = (const float*)d_in[2];
    const float* pre_w1 = (const float*)d_in[3];
    const float* pre_b1 = (const float*)d_in[4];
    const float* cw0_1  = (const float*)d_in[5];
    const float* cw1_1  = (const float*)d_in[6];
    const float* cb_1   = (const float*)d_in[7];
    const float* sw_1   = (const float*)d_in[8];
    const float* sb_1   = (const float*)d_in[9];
    const float* lw_1   = (const float*)d_in[10];
    const float* lb_1   = (const float*)d_in[11];
    const float* pre_w2 = (const float*)d_in[12];
    const float* pre_b2 = (const float*)d_in[13];
    const float* cw0_2  = (const float*)d_in[14];
    const float* cw1_2  = (const float*)d_in[15];
    const float* cb_2   = (const float*)d_in[16];
    const float* sw_2   = (const float*)d_in[17];
    const float* sb_2   = (const float*)d_in[18];
    const float* lw_2   = (const float*)d_in[19];
    const float* lb_2   = (const float*)d_in[20];
    const float* cls_w  = (const float*)d_in[21];
    const float* cls_b  = (const float*)d_in[22];
    float* out = (float*)d_out;

    void *p_xh, *p_tx1, *p_s, *p_xc;
    cudaGetSymbolAddress(&p_xh,  g_xh);
    cudaGetSymbolAddress(&p_tx1, g_tx1);
    cudaGetSymbolAddress(&p_s,   g_s);
    cudaGetSymbolAddress(&p_xc,  g_xc);
    float* xh  = (float*)p_xh;
    float* tx1 = (float*)p_tx1;
    float* s   = (float*)p_s;
    float* xc  = (float*)p_xc;

    static bool attr_done = false;
    if (!attr_done) {
        cudaFuncSetAttribute(cell_post_kernel,
                             cudaFuncAttributeMaxDynamicSharedMemorySize, SMEM_MEGA);
        cudaFuncSetAttribute(gemm_tc_kernel<F_BIAS>,
                             cudaFuncAttributeMaxDynamicSharedMemorySize, SMEM_GEMM);
        attr_done = true;
    }

    const int GB = (NN + 127) / 128;

    // graph prep + CSR build
    prep_zero_kernel<<<(NN + 255)/256, 256>>>();
    prep_edge_kernel<<<(NE + 255)/256, 256>>>(ei, w);
    prep_node_kernel<<<(NN + 255)/256, 256>>>();
    scan1_kernel<<<160, 256>>>();
    scan2_kernel<<<1, 256>>>();
    scan3_kernel<<<160, 256>>>();
    fill_kernel<<<(NE + 255)/256, 256>>>(ei, w);

    // ---- cell 1 ----
    gemm_tc_kernel<F_BIAS><<<GB, 256, SMEM_GEMM>>>(x, pre_w1, pre_b1, xh, NN, FIN, HH);
    aggregate_kernel<<<(NN * 32 + 255) / 256, 256>>>((const float4*)xh, (float4*)tx1, (float4*)s);
    cell_post_kernel<<<GB, 256, SMEM_MEGA>>>(xh, tx1, s, cw0_1, cw1_1, cb_1,
                                             sw_1, sb_1, lw_1, lb_1, xc, NN);
    // ---- cell 2 ----
    gemm_tc_kernel<F_BIAS><<<GB, 256, SMEM_GEMM>>>(xc, pre_w2, pre_b2, xh, NN, HH, HH);
    aggregate_kernel<<<(NN * 32 + 255) / 256, 256>>>((const float4*)xh, (float4*)tx1, (float4*)s);
    cell_post_kernel<<<GB, 256, SMEM_MEGA>>>(xh, tx1, s, cw0_2, cw1_2, cb_2,
                                             sw_2, sb_2, lw_2, lb_2, xc, NN);

    // classifier + log_softmax
    gemm_tc_kernel<F_BIAS><<<GB, 256, SMEM_GEMM>>>(xc, cls_w, cls_b, out, NN, HH, CO);
    logsoftmax_kernel<<<(NN*32 + 255)/256, 256>>>(out);
}